// round 1
// baseline (speedup 1.0000x reference)
#include <cuda_runtime.h>
#include <float.h>

#define HID 4096
#define SLOTS 8
#define HEADS 8
#define BD 512
#define HD 64
#define BB 4
#define SS 4096
#define NH 64   // HEADS*SLOTS

// Scratch (no allocations allowed)
__device__ float g_Q[SLOTS * BD];            // 16 KB
__device__ float g_Qk[NH * HID];             // 1 MB   (scaled by 1/sqrt(HD))
__device__ float g_scores[BB * NH * SS];     // 4 MB   (scores -> attn in place)
__device__ float g_agg[BB * NH * HID];       // 4 MB
__device__ float g_mid[BB * SLOTS * BD];     // 64 KB

// ---------------------------------------------------------------------------
// 1) Q = memory_slots @ Wq^T   (8 x 512), one warp per output
__global__ void k_qproj(const float* __restrict__ ms, const float* __restrict__ Wq) {
    int warp = (blockIdx.x * blockDim.x + threadIdx.x) >> 5;
    int lane = threadIdx.x & 31;
    if (warp >= SLOTS * BD) return;
    int n = warp / BD, c = warp % BD;
    const float* a = ms + n * HID;
    const float* w = Wq + c * HID;
    float acc = 0.f;
    for (int i = lane; i < HID; i += 32) acc += a[i] * w[i];
    #pragma unroll
    for (int off = 16; off; off >>= 1) acc += __shfl_down_sync(0xffffffffu, acc, off);
    if (lane == 0) g_Q[n * BD + c] = acc;
}

// ---------------------------------------------------------------------------
// 2) Qk[j = h*8+n][i] = (1/8) * sum_d Q[n][h*64+d] * Wk[h*64+d][i]
__global__ void k_qk(const float* __restrict__ Wk) {
    __shared__ float qs[HD];
    int j = blockIdx.y;
    int h = j >> 3, n = j & 7;
    if (threadIdx.x < HD) qs[threadIdx.x] = g_Q[n * BD + h * HD + threadIdx.x];
    __syncthreads();
    int i = blockIdx.x * blockDim.x + threadIdx.x;
    float acc = 0.f;
    #pragma unroll 8
    for (int d = 0; d < HD; d++) acc += qs[d] * Wk[(h * HD + d) * HID + i];
    g_Qk[j * HID + i] = acc * 0.125f;
}

// ---------------------------------------------------------------------------
// 3) scores: C[m=(b,s)][j] = H[m,:] . Qk[j,:]   (16384 x 64, K=4096)
//    Written transposed: g_scores[(b*NH + j)*SS + s]
__global__ void k_scores(const float* __restrict__ H) {
    __shared__ float As[64][33];   // H tile   [m][k]
    __shared__ float Bs[64][33];   // Qk tile  [j][k]
    int tid = threadIdx.x;
    int tx = tid & 15, ty = tid >> 4;
    int m0 = blockIdx.x * 64;
    float acc[4][4] = {};
    for (int kt = 0; kt < HID; kt += 32) {
        #pragma unroll
        for (int l = 0; l < 8; l++) {
            int e = tid + l * 256;
            int r = e >> 5, c = e & 31;
            As[r][c] = H[(m0 + r) * HID + kt + c];
            Bs[r][c] = g_Qk[r * HID + kt + c];
        }
        __syncthreads();
        #pragma unroll
        for (int k = 0; k < 32; k++) {
            float a[4], b[4];
            #pragma unroll
            for (int x = 0; x < 4; x++) a[x] = As[ty * 4 + x][k];
            #pragma unroll
            for (int y = 0; y < 4; y++) b[y] = Bs[tx * 4 + y][k];
            #pragma unroll
            for (int x = 0; x < 4; x++)
                #pragma unroll
                for (int y = 0; y < 4; y++) acc[x][y] += a[x] * b[y];
        }
        __syncthreads();
    }
    #pragma unroll
    for (int x = 0; x < 4; x++) {
        int m = m0 + ty * 4 + x;
        int b = m >> 12, s = m & 4095;
        #pragma unroll
        for (int y = 0; y < 4; y++) {
            int j = tx * 4 + y;
            g_scores[((b * NH + j) << 12) + s] = acc[x][y];
        }
    }
}

// ---------------------------------------------------------------------------
// 4) masked softmax over s (rows of length 4096), in place
__global__ void k_softmax(const int* __restrict__ mask) {
    __shared__ float red[256];
    int row = blockIdx.x;            // b*NH + j
    int b = row >> 6;
    float* sc = g_scores + row * SS;
    const int* mrow = mask + b * SS;
    int tid = threadIdx.x;
    float v[16];
    float mx = -FLT_MAX;
    #pragma unroll
    for (int k = 0; k < 16; k++) {
        int s = k * 256 + tid;
        float val = (mrow[s] == 0) ? -FLT_MAX : sc[s];
        v[k] = val;
        mx = fmaxf(mx, val);
    }
    red[tid] = mx; __syncthreads();
    for (int o = 128; o; o >>= 1) { if (tid < o) red[tid] = fmaxf(red[tid], red[tid + o]); __syncthreads(); }
    mx = red[0]; __syncthreads();
    float sum = 0.f;
    #pragma unroll
    for (int k = 0; k < 16; k++) { v[k] = __expf(v[k] - mx); sum += v[k]; }
    red[tid] = sum; __syncthreads();
    for (int o = 128; o; o >>= 1) { if (tid < o) red[tid] += red[tid + o]; __syncthreads(); }
    float inv = 1.f / red[0];
    #pragma unroll
    for (int k = 0; k < 16; k++) sc[k * 256 + tid] = v[k] * inv;
}

// ---------------------------------------------------------------------------
// 5) agg[b][j][i] = sum_s attn[b][j][s] * H[b][s][i]   (per b: 64 x 4096, K=4096)
__global__ void k_agg(const float* __restrict__ H) {
    __shared__ float As[64][33];   // attn [j][ks]
    __shared__ float Bs[32][65];   // H    [ks][i]
    int b = blockIdx.y;
    int i0 = blockIdx.x * 64;
    int tid = threadIdx.x;
    int tx = tid & 15, ty = tid >> 4;
    const float* A = g_scores + b * NH * SS;
    const float* Hb = H + b * SS * HID;
    float acc[4][4] = {};
    for (int st = 0; st < SS; st += 32) {
        #pragma unroll
        for (int l = 0; l < 8; l++) {
            int e = tid + l * 256;
            int r = e >> 5, c = e & 31;
            As[r][c] = A[r * SS + st + c];
        }
        #pragma unroll
        for (int l = 0; l < 8; l++) {
            int e = tid + l * 256;
            int r = e >> 6, c = e & 63;
            Bs[r][c] = Hb[(st + r) * HID + i0 + c];
        }
        __syncthreads();
        #pragma unroll
        for (int k = 0; k < 32; k++) {
            float a[4], bb[4];
            #pragma unroll
            for (int x = 0; x < 4; x++) a[x] = As[ty * 4 + x][k];
            #pragma unroll
            for (int y = 0; y < 4; y++) bb[y] = Bs[k][tx * 4 + y];
            #pragma unroll
            for (int x = 0; x < 4; x++)
                #pragma unroll
                for (int y = 0; y < 4; y++) acc[x][y] += a[x] * bb[y];
        }
        __syncthreads();
    }
    #pragma unroll
    for (int x = 0; x < 4; x++) {
        int j = ty * 4 + x;
        #pragma unroll
        for (int y = 0; y < 4; y++)
            g_agg[((b * NH + j) << 12) + i0 + tx * 4 + y] = acc[x][y];
    }
}

// ---------------------------------------------------------------------------
// 6) g_mid[(b,n)][h*64+d] = agg[b][h*8+n][:] . Wv[h*64+d][:]
__global__ void k_mid(const float* __restrict__ Wv) {
    __shared__ float As[8][65];
    __shared__ float Bs[64][65];
    int h = blockIdx.x, b = blockIdx.y;
    int tid = threadIdx.x;
    float acc0 = 0.f, acc1 = 0.f;
    int o0 = tid, o1 = tid + 256;
    int n0 = o0 >> 6, d0 = o0 & 63;
    int n1 = o1 >> 6, d1 = o1 & 63;
    for (int kt = 0; kt < HID; kt += 64) {
        {
            int e = tid; int r = e >> 6, c = e & 63;
            As[r][c] = g_agg[(b * NH + h * SLOTS + r) * HID + kt + c];
            e = tid + 256; r = e >> 6; c = e & 63;
            As[r][c] = g_agg[(b * NH + h * SLOTS + r) * HID + kt + c];
        }
        #pragma unroll
        for (int l = 0; l < 16; l++) {
            int e = tid + l * 256;
            int r = e >> 6, c = e & 63;
            Bs[r][c] = Wv[(h * HD + r) * HID + kt + c];
        }
        __syncthreads();
        #pragma unroll
        for (int k = 0; k < 64; k++) {
            acc0 += As[n0][k] * Bs[d0][k];
            acc1 += As[n1][k] * Bs[d1][k];
        }
        __syncthreads();
    }
    g_mid[(b * SLOTS + n0) * BD + h * HD + d0] = acc0;
    g_mid[(b * SLOTS + n1) * BD + h * HD + d1] = acc1;
}

// ---------------------------------------------------------------------------
// 7) final[m=(b,n)][o] = g_mid[m][:] . Wo[o][:]   (32 x 4096, K=512)
__global__ void k_final(const float* __restrict__ Wo, float* __restrict__ out) {
    __shared__ float As[32][65];
    __shared__ float Bs[128][65];
    int tid = threadIdx.x;
    int tx = tid & 31, ty = tid >> 5;
    int o0 = blockIdx.x * 128;
    float acc[4][4] = {};
    for (int kt = 0; kt < BD; kt += 64) {
        #pragma unroll
        for (int l = 0; l < 8; l++) {
            int e = tid + l * 256;
            int r = e >> 6, c = e & 63;
            As[r][c] = g_mid[r * BD + kt + c];
        }
        #pragma unroll
        for (int l = 0; l < 32; l++) {
            int e = tid + l * 256;
            int r = e >> 6, c = e & 63;
            Bs[r][c] = Wo[(o0 + r) * BD + kt + c];
        }
        __syncthreads();
        #pragma unroll
        for (int k = 0; k < 64; k++) {
            float a[4], bb[4];
            #pragma unroll
            for (int x = 0; x < 4; x++) a[x] = As[ty * 4 + x][k];
            #pragma unroll
            for (int y = 0; y < 4; y++) bb[y] = Bs[tx * 4 + y][k];
            #pragma unroll
            for (int x = 0; x < 4; x++)
                #pragma unroll
                for (int y = 0; y < 4; y++) acc[x][y] += a[x] * bb[y];
        }
        __syncthreads();
    }
    #pragma unroll
    for (int x = 0; x < 4; x++)
        #pragma unroll
        for (int y = 0; y < 4; y++)
            out[(ty * 4 + x) * HID + o0 + tx * 4 + y] = acc[x][y];
}

// ---------------------------------------------------------------------------
extern "C" void kernel_launch(void* const* d_in, const int* in_sizes, int n_in,
                              void* d_out, int out_size) {
    const float* H    = (const float*)d_in[0];
    const int*   mask = (const int*)d_in[1];
    const float* ms   = (const float*)d_in[2];
    const float* Wq   = (const float*)d_in[3];
    const float* Wk   = (const float*)d_in[4];
    const float* Wv   = (const float*)d_in[5];
    const float* Wo   = (const float*)d_in[6];
    float* out = (float*)d_out;

    k_qproj <<<512, 256>>>(ms, Wq);
    k_qk    <<<dim3(HID / 256, NH), 256>>>(Wk);
    k_scores<<<(BB * SS) / 64, 256>>>(H);
    k_softmax<<<BB * NH, 256>>>(mask);
    k_agg   <<<dim3(HID / 64, BB), 256>>>(H);
    k_mid   <<<dim3(HEADS, BB), 256>>>(Wv);
    k_final <<<HID / 128, 256>>>(Wo, out);
}

// round 2
// speedup vs baseline: 1.4057x; 1.4057x over previous
#include <cuda_runtime.h>
#include <float.h>
#include <stdint.h>

#define HID 4096
#define SLOTS 8
#define HEADS 8
#define BD 512
#define HD 64
#define BB 4
#define SS 4096
#define NH 64   // HEADS*SLOTS

// Scratch (no allocations allowed)
__device__ float g_Q[SLOTS * BD];            // 16 KB
__device__ float g_Qk[NH * HID];             // 1 MB   (scaled by 1/sqrt(HD))
__device__ float g_scores[BB * NH * SS];     // 4 MB   (scores -> attn in place)
__device__ float g_agg[BB * NH * HID];       // 4 MB
__device__ float g_mid[BB * SLOTS * BD];     // 64 KB

__device__ __forceinline__ uint32_t f2tf(float f) {
    uint32_t u;
    asm("cvt.rna.tf32.f32 %0, %1;" : "=r"(u) : "f"(f));
    return u;
}

__device__ __forceinline__ void mma_tf32(float* d, const uint32_t* a, const uint32_t* b) {
    asm volatile(
        "mma.sync.aligned.m16n8k8.row.col.f32.tf32.tf32.f32 "
        "{%0,%1,%2,%3}, {%4,%5,%6,%7}, {%8,%9}, {%0,%1,%2,%3};"
        : "+f"(d[0]), "+f"(d[1]), "+f"(d[2]), "+f"(d[3])
        : "r"(a[0]), "r"(a[1]), "r"(a[2]), "r"(a[3]), "r"(b[0]), "r"(b[1]));
}

// ---------------------------------------------------------------------------
// 1) Q = memory_slots @ Wq^T   (8 x 512), one warp per output
__global__ void k_qproj(const float* __restrict__ ms, const float* __restrict__ Wq) {
    int warp = (blockIdx.x * blockDim.x + threadIdx.x) >> 5;
    int lane = threadIdx.x & 31;
    if (warp >= SLOTS * BD) return;
    int n = warp / BD, c = warp % BD;
    const float* a = ms + n * HID;
    const float* w = Wq + c * HID;
    float acc = 0.f;
    for (int i = lane; i < HID; i += 32) acc += a[i] * w[i];
    #pragma unroll
    for (int off = 16; off; off >>= 1) acc += __shfl_down_sync(0xffffffffu, acc, off);
    if (lane == 0) g_Q[n * BD + c] = acc;
}

// ---------------------------------------------------------------------------
// 2) Qk[j = h*8+n][i] = (1/8) * sum_d Q[n][h*64+d] * Wk[h*64+d][i]
__global__ void k_qk(const float* __restrict__ Wk) {
    __shared__ float qs[HD];
    int j = blockIdx.y;
    int h = j >> 3, n = j & 7;
    if (threadIdx.x < HD) qs[threadIdx.x] = g_Q[n * BD + h * HD + threadIdx.x];
    __syncthreads();
    int i = blockIdx.x * blockDim.x + threadIdx.x;
    float acc = 0.f;
    #pragma unroll 8
    for (int d = 0; d < HD; d++) acc += qs[d] * Wk[(h * HD + d) * HID + i];
    g_Qk[j * HID + i] = acc * 0.125f;
}

// ---------------------------------------------------------------------------
// 3) scores via tf32 MMA: C[m=(b,s)][j] = H[m,:] . Qk[j,:]
//    CTA tile 128m x 64j, K chunk 32. Written transposed via smem staging.
#define SA 36
#define SB 36
__global__ void k_scores(const float* __restrict__ H) {
    __shared__ float sm[8320];          // As(128*36=4608) + Bs(64*36=2304) / Cs(64*130)
    float* As = sm;
    float* Bs = sm + 128 * SA;
    int tid = threadIdx.x;
    int lane = tid & 31, w = tid >> 5;
    int wm = w & 3, wn = w >> 2;        // 4 x 2 warp grid
    int R = wm * 32, C = wn * 32;
    int m0 = blockIdx.x * 128;
    int ar = lane >> 2, ac = lane & 3;

    float acc[2][4][4];
    #pragma unroll
    for (int t = 0; t < 2; t++)
        #pragma unroll
        for (int n = 0; n < 4; n++)
            #pragma unroll
            for (int q = 0; q < 4; q++) acc[t][n][q] = 0.f;

    for (int kt = 0; kt < HID; kt += 32) {
        // load A tile 128x32 (4 passes of 256 float4)
        #pragma unroll
        for (int p = 0; p < 4; p++) {
            int r = p * 32 + (tid >> 3);
            int c = (tid & 7) * 4;
            float4 v = *(const float4*)&H[(size_t)(m0 + r) * HID + kt + c];
            float4 o;
            o.x = __uint_as_float(f2tf(v.x));
            o.y = __uint_as_float(f2tf(v.y));
            o.z = __uint_as_float(f2tf(v.z));
            o.w = __uint_as_float(f2tf(v.w));
            *(float4*)&As[r * SA + c] = o;
        }
        // load B tile 64x32 (2 passes)
        #pragma unroll
        for (int p = 0; p < 2; p++) {
            int r = p * 32 + (tid >> 3);
            int c = (tid & 7) * 4;
            float4 v = *(const float4*)&g_Qk[r * HID + kt + c];
            float4 o;
            o.x = __uint_as_float(f2tf(v.x));
            o.y = __uint_as_float(f2tf(v.y));
            o.z = __uint_as_float(f2tf(v.z));
            o.w = __uint_as_float(f2tf(v.w));
            *(float4*)&Bs[r * SB + c] = o;
        }
        __syncthreads();
        #pragma unroll
        for (int kk = 0; kk < 32; kk += 8) {
            uint32_t a[2][4], b[4][2];
            #pragma unroll
            for (int t = 0; t < 2; t++) {
                int rb = R + t * 16 + ar;
                a[t][0] = __float_as_uint(As[rb * SA + kk + ac]);
                a[t][1] = __float_as_uint(As[(rb + 8) * SA + kk + ac]);
                a[t][2] = __float_as_uint(As[rb * SA + kk + ac + 4]);
                a[t][3] = __float_as_uint(As[(rb + 8) * SA + kk + ac + 4]);
            }
            #pragma unroll
            for (int n = 0; n < 4; n++) {
                int cb = C + n * 8 + ar;
                b[n][0] = __float_as_uint(Bs[cb * SB + kk + ac]);
                b[n][1] = __float_as_uint(Bs[cb * SB + kk + ac + 4]);
            }
            #pragma unroll
            for (int t = 0; t < 2; t++)
                #pragma unroll
                for (int n = 0; n < 4; n++)
                    mma_tf32(acc[t][n], a[t], b[n]);
        }
        __syncthreads();
    }

    // stage C (128m x 64j) into smem transposed as Cs[j][m], stride 130
    float* Cs = sm;
    #pragma unroll
    for (int t = 0; t < 2; t++) {
        #pragma unroll
        for (int n = 0; n < 4; n++) {
            int row = R + t * 16 + ar;
            int col = C + n * 8 + 2 * ac;
            Cs[col * 130 + row]            = acc[t][n][0];
            Cs[(col + 1) * 130 + row]      = acc[t][n][1];
            Cs[col * 130 + row + 8]        = acc[t][n][2];
            Cs[(col + 1) * 130 + row + 8]  = acc[t][n][3];
        }
    }
    __syncthreads();
    int b = m0 >> 12;
    int s0 = m0 & 4095;
    #pragma unroll
    for (int l = 0; l < 32; l++) {
        int e = l * 256 + tid;
        int j = e >> 7, m = e & 127;
        g_scores[((b * NH + j) << 12) + s0 + m] = Cs[j * 130 + m];
    }
}

// ---------------------------------------------------------------------------
// 4) masked softmax over s (rows of length 4096), in place
__global__ void k_softmax(const int* __restrict__ mask) {
    __shared__ float red[256];
    int row = blockIdx.x;            // b*NH + j
    int b = row >> 6;
    float* sc = g_scores + row * SS;
    const int* mrow = mask + b * SS;
    int tid = threadIdx.x;
    float v[16];
    float mx = -FLT_MAX;
    #pragma unroll
    for (int k = 0; k < 16; k++) {
        int s = k * 256 + tid;
        float val = (mrow[s] == 0) ? -FLT_MAX : sc[s];
        v[k] = val;
        mx = fmaxf(mx, val);
    }
    red[tid] = mx; __syncthreads();
    for (int o = 128; o; o >>= 1) { if (tid < o) red[tid] = fmaxf(red[tid], red[tid + o]); __syncthreads(); }
    mx = red[0]; __syncthreads();
    float sum = 0.f;
    #pragma unroll
    for (int k = 0; k < 16; k++) { v[k] = __expf(v[k] - mx); sum += v[k]; }
    red[tid] = sum; __syncthreads();
    for (int o = 128; o; o >>= 1) { if (tid < o) red[tid] += red[tid + o]; __syncthreads(); }
    float inv = 1.f / red[0];
    #pragma unroll
    for (int k = 0; k < 16; k++) sc[k * 256 + tid] = v[k] * inv;
}

// ---------------------------------------------------------------------------
// 5) agg via tf32 MMA: agg[b][j][i] = sum_s attn[b][j][s] * H[b][s][i]
//    CTA tile 64j x 128i, K chunk 32 over s.
#define SHS 132
__global__ void k_agg(const float* __restrict__ H) {
    __shared__ float sm[64 * SA + 32 * SHS];   // As(2304) + Hs(4224)
    float* As = sm;
    float* Hs = sm + 64 * SA;
    int tid = threadIdx.x;
    int lane = tid & 31, w = tid >> 5;
    int wm = w >> 2, wn = w & 3;               // 2 x 4 warp grid
    int R = wm * 32, C = wn * 32;
    int b = blockIdx.y;
    int i0 = blockIdx.x * 128;
    int ar = lane >> 2, ac = lane & 3;

    float acc[2][4][4];
    #pragma unroll
    for (int t = 0; t < 2; t++)
        #pragma unroll
        for (int n = 0; n < 4; n++)
            #pragma unroll
            for (int q = 0; q < 4; q++) acc[t][n][q] = 0.f;

    const float* Hb = H + (size_t)b * SS * HID;
    const float* A  = g_scores + b * NH * SS;

    for (int st = 0; st < SS; st += 32) {
        // attn tile 64x32 (2 passes of 256 float4)
        #pragma unroll
        for (int p = 0; p < 2; p++) {
            int r = p * 32 + (tid >> 3);
            int c = (tid & 7) * 4;
            float4 v = *(const float4*)&A[r * SS + st + c];
            float4 o;
            o.x = __uint_as_float(f2tf(v.x));
            o.y = __uint_as_float(f2tf(v.y));
            o.z = __uint_as_float(f2tf(v.z));
            o.w = __uint_as_float(f2tf(v.w));
            *(float4*)&As[r * SA + c] = o;
        }
        // H tile 32s x 128i (4 passes: one warp per row)
        #pragma unroll
        for (int p = 0; p < 4; p++) {
            int r = p * 8 + (tid >> 5);
            int c = (tid & 31) * 4;
            float4 v = *(const float4*)&Hb[(size_t)(st + r) * HID + i0 + c];
            float4 o;
            o.x = __uint_as_float(f2tf(v.x));
            o.y = __uint_as_float(f2tf(v.y));
            o.z = __uint_as_float(f2tf(v.z));
            o.w = __uint_as_float(f2tf(v.w));
            *(float4*)&Hs[r * SHS + c] = o;
        }
        __syncthreads();
        #pragma unroll
        for (int kk = 0; kk < 32; kk += 8) {
            uint32_t a[2][4], bfr[4][2];
            #pragma unroll
            for (int t = 0; t < 2; t++) {
                int rb = R + t * 16 + ar;
                a[t][0] = __float_as_uint(As[rb * SA + kk + ac]);
                a[t][1] = __float_as_uint(As[(rb + 8) * SA + kk + ac]);
                a[t][2] = __float_as_uint(As[rb * SA + kk + ac + 4]);
                a[t][3] = __float_as_uint(As[(rb + 8) * SA + kk + ac + 4]);
            }
            #pragma unroll
            for (int n = 0; n < 4; n++) {
                int cb = C + n * 8 + ar;
                bfr[n][0] = __float_as_uint(Hs[(kk + ac) * SHS + cb]);
                bfr[n][1] = __float_as_uint(Hs[(kk + ac + 4) * SHS + cb]);
            }
            #pragma unroll
            for (int t = 0; t < 2; t++)
                #pragma unroll
                for (int n = 0; n < 4; n++)
                    mma_tf32(acc[t][n], a[t], bfr[n]);
        }
        __syncthreads();
    }

    // direct float2 stores: row j, cols (i, i+1)
    #pragma unroll
    for (int t = 0; t < 2; t++) {
        #pragma unroll
        for (int n = 0; n < 4; n++) {
            int j = R + t * 16 + ar;
            int i = C + n * 8 + 2 * ac;
            float2 v0 = make_float2(acc[t][n][0], acc[t][n][1]);
            float2 v1 = make_float2(acc[t][n][2], acc[t][n][3]);
            *(float2*)&g_agg[(size_t)(b * NH + j) * HID + i0 + i]       = v0;
            *(float2*)&g_agg[(size_t)(b * NH + j + 8) * HID + i0 + i]   = v1;
        }
    }
}

// ---------------------------------------------------------------------------
// 6) g_mid[(b,n)][h*64+d] = agg[b][h*8+n][:] . Wv[h*64+d][:]
__global__ void k_mid(const float* __restrict__ Wv) {
    __shared__ float As[8][65];
    __shared__ float Bs[64][65];
    int h = blockIdx.x, b = blockIdx.y;
    int tid = threadIdx.x;
    float acc0 = 0.f, acc1 = 0.f;
    int o0 = tid, o1 = tid + 256;
    int n0 = o0 >> 6, d0 = o0 & 63;
    int n1 = o1 >> 6, d1 = o1 & 63;
    for (int kt = 0; kt < HID; kt += 64) {
        {
            int e = tid; int r = e >> 6, c = e & 63;
            As[r][c] = g_agg[(b * NH + h * SLOTS + r) * HID + kt + c];
            e = tid + 256; r = e >> 6; c = e & 63;
            As[r][c] = g_agg[(b * NH + h * SLOTS + r) * HID + kt + c];
        }
        #pragma unroll
        for (int l = 0; l < 16; l++) {
            int e = tid + l * 256;
            int r = e >> 6, c = e & 63;
            Bs[r][c] = Wv[(h * HD + r) * HID + kt + c];
        }
        __syncthreads();
        #pragma unroll
        for (int k = 0; k < 64; k++) {
            acc0 += As[n0][k] * Bs[d0][k];
            acc1 += As[n1][k] * Bs[d1][k];
        }
        __syncthreads();
    }
    g_mid[(b * SLOTS + n0) * BD + h * HD + d0] = acc0;
    g_mid[(b * SLOTS + n1) * BD + h * HD + d1] = acc1;
}

// ---------------------------------------------------------------------------
// 7) final[m=(b,n)][o] = g_mid[m][:] . Wo[o][:]   (32 x 4096, K=512)
__global__ void k_final(const float* __restrict__ Wo, float* __restrict__ out) {
    __shared__ float As[32][65];
    __shared__ float Bs[128][65];
    int tid = threadIdx.x;
    int tx = tid & 31, ty = tid >> 5;
    int o0 = blockIdx.x * 128;
    float acc[4][4] = {};
    for (int kt = 0; kt < BD; kt += 64) {
        #pragma unroll
        for (int l = 0; l < 8; l++) {
            int e = tid + l * 256;
            int r = e >> 6, c = e & 63;
            As[r][c] = g_mid[r * BD + kt + c];
        }
        #pragma unroll
        for (int l = 0; l < 32; l++) {
            int e = tid + l * 256;
            int r = e >> 6, c = e & 63;
            Bs[r][c] = Wo[(o0 + r) * BD + kt + c];
        }
        __syncthreads();
        #pragma unroll
        for (int k = 0; k < 64; k++) {
            float a[4], bb[4];
            #pragma unroll
            for (int x = 0; x < 4; x++) a[x] = As[ty * 4 + x][k];
            #pragma unroll
            for (int y = 0; y < 4; y++) bb[y] = Bs[tx * 4 + y][k];
            #pragma unroll
            for (int x = 0; x < 4; x++)
                #pragma unroll
                for (int y = 0; y < 4; y++) acc[x][y] += a[x] * bb[y];
        }
        __syncthreads();
    }
    #pragma unroll
    for (int x = 0; x < 4; x++)
        #pragma unroll
        for (int y = 0; y < 4; y++)
            out[(ty * 4 + x) * HID + o0 + tx * 4 + y] = acc[x][y];
}

// ---------------------------------------------------------------------------
extern "C" void kernel_launch(void* const* d_in, const int* in_sizes, int n_in,
                              void* d_out, int out_size) {
    const float* H    = (const float*)d_in[0];
    const int*   mask = (const int*)d_in[1];
    const float* ms   = (const float*)d_in[2];
    const float* Wq   = (const float*)d_in[3];
    const float* Wk   = (const float*)d_in[4];
    const float* Wv   = (const float*)d_in[5];
    const float* Wo   = (const float*)d_in[6];
    float* out = (float*)d_out;

    k_qproj <<<512, 256>>>(ms, Wq);
    k_qk    <<<dim3(HID / 256, NH), 256>>>(Wk);
    k_scores<<<(BB * SS) / 128, 256>>>(H);
    k_softmax<<<BB * NH, 256>>>(mask);
    k_agg   <<<dim3(HID / 128, BB), 256>>>(H);
    k_mid   <<<dim3(HEADS, BB), 256>>>(Wv);
    k_final <<<HID / 128, 256>>>(Wo, out);
}

// round 3
// speedup vs baseline: 2.3661x; 1.6832x over previous
#include <cuda_runtime.h>
#include <float.h>
#include <stdint.h>

#define HID 4096
#define SLOTS 8
#define HEADS 8
#define BD 512
#define HD 64
#define BB 4
#define SS 4096
#define NH 64   // HEADS*SLOTS

// Scratch (no allocations allowed)
__device__ float g_Q[SLOTS * BD];            // 16 KB
__device__ float g_Qk[NH * HID];             // 1 MB   (tf32-rounded, scaled by 1/8)
__device__ float g_scores[BB * NH * SS];     // 4 MB   (scores -> attn in place)
__device__ float g_agg[BB * NH * HID];       // 4 MB
__device__ float g_mid[BB * SLOTS * BD];     // 64 KB

__device__ __forceinline__ uint32_t f2tf(float f) {
    uint32_t u;
    asm("cvt.rna.tf32.f32 %0, %1;" : "=r"(u) : "f"(f));
    return u;
}

__device__ __forceinline__ void mma_tf32(float* d, const uint32_t* a, const uint32_t* b) {
    asm volatile(
        "mma.sync.aligned.m16n8k8.row.col.f32.tf32.tf32.f32 "
        "{%0,%1,%2,%3}, {%4,%5,%6,%7}, {%8,%9}, {%0,%1,%2,%3};"
        : "+f"(d[0]), "+f"(d[1]), "+f"(d[2]), "+f"(d[3])
        : "r"(a[0]), "r"(a[1]), "r"(a[2]), "r"(a[3]), "r"(b[0]), "r"(b[1]));
}

__device__ __forceinline__ void cp16(uint32_t smem_dst, const float* gsrc) {
    asm volatile("cp.async.cg.shared.global [%0], [%1], 16;" :: "r"(smem_dst), "l"(gsrc));
}
#define CP_COMMIT asm volatile("cp.async.commit_group;")
#define CP_WAIT1  asm volatile("cp.async.wait_group 1;")

// ---------------------------------------------------------------------------
// 1) Q = memory_slots @ Wq^T   (8 x 512), one warp per output
__global__ void k_qproj(const float* __restrict__ ms, const float* __restrict__ Wq) {
    int warp = (blockIdx.x * blockDim.x + threadIdx.x) >> 5;
    int lane = threadIdx.x & 31;
    if (warp >= SLOTS * BD) return;
    int n = warp / BD, c = warp % BD;
    const float* a = ms + n * HID;
    const float* w = Wq + c * HID;
    float acc = 0.f;
    for (int i = lane; i < HID; i += 32) acc += a[i] * w[i];
    #pragma unroll
    for (int off = 16; off; off >>= 1) acc += __shfl_down_sync(0xffffffffu, acc, off);
    if (lane == 0) g_Q[n * BD + c] = acc;
}

// ---------------------------------------------------------------------------
// 2) Qk[j = h*8+n][i] = (1/8) * sum_d Q[n][h*64+d] * Wk[h*64+d][i]  (tf32-rounded)
__global__ void k_qk(const float* __restrict__ Wk) {
    __shared__ float qs[HD];
    int j = blockIdx.y;
    int h = j >> 3, n = j & 7;
    if (threadIdx.x < HD) qs[threadIdx.x] = g_Q[n * BD + h * HD + threadIdx.x];
    __syncthreads();
    int i = blockIdx.x * blockDim.x + threadIdx.x;
    float acc = 0.f;
    #pragma unroll 8
    for (int d = 0; d < HD; d++) acc += qs[d] * Wk[(h * HD + d) * HID + i];
    g_Qk[j * HID + i] = __uint_as_float(f2tf(acc * 0.125f));
}

// ---------------------------------------------------------------------------
// 3) scores via tf32 MMA, 3-stage cp.async pipeline.
//    C[m=(b,s)][j] = H[m,:] . Qk[j,:]; CTA tile 128m x 64j, K chunk 32.
#define SA 36
#define S_STAGE (128 * SA + 64 * SA)   // 6912 floats per stage
__global__ void k_scores(const float* __restrict__ H) {
    extern __shared__ float sm[];
    int tid = threadIdx.x;
    int lane = tid & 31, w = tid >> 5;
    int wm = w & 3, wn = w >> 2;        // 4 x 2 warp grid
    int R = wm * 32, C = wn * 32;
    int m0 = blockIdx.x * 128;
    int ar = lane >> 2, ac = lane & 3;

    uint32_t smem_u32 = (uint32_t)__cvta_generic_to_shared(sm);

    float acc[2][4][4];
    #pragma unroll
    for (int t = 0; t < 2; t++)
        #pragma unroll
        for (int n = 0; n < 4; n++)
            #pragma unroll
            for (int q = 0; q < 4; q++) acc[t][n][q] = 0.f;

    // per-thread load coordinates
    int lra = tid >> 3;            // A rows (stride 32 per pass)
    int lca = (tid & 7) * 4;

    auto issue = [&](int stage, int kt) {
        uint32_t base = smem_u32 + stage * S_STAGE * 4;
        #pragma unroll
        for (int p = 0; p < 4; p++) {
            int r = p * 32 + lra;
            cp16(base + (r * SA + lca) * 4, &H[(size_t)(m0 + r) * HID + kt + lca]);
        }
        uint32_t bbase = base + 128 * SA * 4;
        #pragma unroll
        for (int p = 0; p < 2; p++) {
            int r = p * 32 + lra;
            cp16(bbase + (r * SA + lca) * 4, &g_Qk[r * HID + kt + lca]);
        }
    };

    issue(0, 0); CP_COMMIT;
    issue(1, 32); CP_COMMIT;

    const int NIT = HID / 32;   // 128
    for (int it = 0; it < NIT; it++) {
        CP_WAIT1;
        __syncthreads();
        if (it + 2 < NIT) issue((it + 2) % 3, (it + 2) * 32);
        CP_COMMIT;
        float* As = sm + (it % 3) * S_STAGE;
        float* Bs = As + 128 * SA;
        #pragma unroll
        for (int kk = 0; kk < 32; kk += 8) {
            uint32_t a[2][4], b[4][2];
            #pragma unroll
            for (int t = 0; t < 2; t++) {
                int rb = R + t * 16 + ar;
                a[t][0] = __float_as_uint(As[rb * SA + kk + ac]);
                a[t][1] = __float_as_uint(As[(rb + 8) * SA + kk + ac]);
                a[t][2] = __float_as_uint(As[rb * SA + kk + ac + 4]);
                a[t][3] = __float_as_uint(As[(rb + 8) * SA + kk + ac + 4]);
            }
            #pragma unroll
            for (int n = 0; n < 4; n++) {
                int cb = C + n * 8 + ar;
                b[n][0] = __float_as_uint(Bs[cb * SA + kk + ac]);
                b[n][1] = __float_as_uint(Bs[cb * SA + kk + ac + 4]);
            }
            #pragma unroll
            for (int t = 0; t < 2; t++)
                #pragma unroll
                for (int n = 0; n < 4; n++)
                    mma_tf32(acc[t][n], a[t], b[n]);
        }
    }
    __syncthreads();

    // stage C (128m x 64j) into smem transposed as Cs[j][m], stride 130
    float* Cs = sm;
    #pragma unroll
    for (int t = 0; t < 2; t++) {
        #pragma unroll
        for (int n = 0; n < 4; n++) {
            int row = R + t * 16 + ar;
            int col = C + n * 8 + 2 * ac;
            Cs[col * 130 + row]            = acc[t][n][0];
            Cs[(col + 1) * 130 + row]      = acc[t][n][1];
            Cs[col * 130 + row + 8]        = acc[t][n][2];
            Cs[(col + 1) * 130 + row + 8]  = acc[t][n][3];
        }
    }
    __syncthreads();
    int b = m0 >> 12;
    int s0 = m0 & 4095;
    #pragma unroll
    for (int l = 0; l < 32; l++) {
        int e = l * 256 + tid;
        int j = e >> 7, m = e & 127;
        g_scores[((b * NH + j) << 12) + s0 + m] = Cs[j * 130 + m];
    }
}

// ---------------------------------------------------------------------------
// 4) masked softmax over s, in place; stores tf32-rounded probs
__global__ void k_softmax(const int* __restrict__ mask) {
    __shared__ float red[256];
    int row = blockIdx.x;            // b*NH + j
    int b = row >> 6;
    float* sc = g_scores + row * SS;
    const int* mrow = mask + b * SS;
    int tid = threadIdx.x;
    float v[16];
    float mx = -FLT_MAX;
    #pragma unroll
    for (int k = 0; k < 16; k++) {
        int s = k * 256 + tid;
        float val = (mrow[s] == 0) ? -FLT_MAX : sc[s];
        v[k] = val;
        mx = fmaxf(mx, val);
    }
    red[tid] = mx; __syncthreads();
    for (int o = 128; o; o >>= 1) { if (tid < o) red[tid] = fmaxf(red[tid], red[tid + o]); __syncthreads(); }
    mx = red[0]; __syncthreads();
    float sum = 0.f;
    #pragma unroll
    for (int k = 0; k < 16; k++) { v[k] = __expf(v[k] - mx); sum += v[k]; }
    red[tid] = sum; __syncthreads();
    for (int o = 128; o; o >>= 1) { if (tid < o) red[tid] += red[tid + o]; __syncthreads(); }
    float inv = 1.f / red[0];
    #pragma unroll
    for (int k = 0; k < 16; k++) sc[k * 256 + tid] = __uint_as_float(f2tf(v[k] * inv));
}

// ---------------------------------------------------------------------------
// 5) agg via tf32 MMA, 3-stage cp.async pipeline.
//    agg[b][j][i] = sum_s attn[b][j][s] * H[b][s][i]; CTA tile 64j x 128i.
#define SHS 132
#define G_STAGE (64 * SA + 32 * SHS)   // 6528 floats per stage
__global__ void k_agg(const float* __restrict__ H) {
    extern __shared__ float sm[];
    int tid = threadIdx.x;
    int lane = tid & 31, w = tid >> 5;
    int wm = w >> 2, wn = w & 3;               // 2 x 4 warp grid
    int R = wm * 32, C = wn * 32;
    int b = blockIdx.y;
    int i0 = blockIdx.x * 128;
    int ar = lane >> 2, ac = lane & 3;

    uint32_t smem_u32 = (uint32_t)__cvta_generic_to_shared(sm);

    float acc[2][4][4];
    #pragma unroll
    for (int t = 0; t < 2; t++)
        #pragma unroll
        for (int n = 0; n < 4; n++)
            #pragma unroll
            for (int q = 0; q < 4; q++) acc[t][n][q] = 0.f;

    const float* Hb = H + (size_t)b * SS * HID;
    const float* A  = g_scores + b * NH * SS;

    int lra = tid >> 3;
    int lca = (tid & 7) * 4;
    int hr = tid >> 5;
    int hc = (tid & 31) * 4;

    auto issue = [&](int stage, int st) {
        uint32_t base = smem_u32 + stage * G_STAGE * 4;
        #pragma unroll
        for (int p = 0; p < 2; p++) {
            int r = p * 32 + lra;
            cp16(base + (r * SA + lca) * 4, &A[r * SS + st + lca]);
        }
        uint32_t hbase = base + 64 * SA * 4;
        #pragma unroll
        for (int p = 0; p < 4; p++) {
            int r = p * 8 + hr;
            cp16(hbase + (r * SHS + hc) * 4, &Hb[(size_t)(st + r) * HID + i0 + hc]);
        }
    };

    issue(0, 0); CP_COMMIT;
    issue(1, 32); CP_COMMIT;

    const int NIT = SS / 32;   // 128
    for (int it = 0; it < NIT; it++) {
        CP_WAIT1;
        __syncthreads();
        if (it + 2 < NIT) issue((it + 2) % 3, (it + 2) * 32);
        CP_COMMIT;
        float* As = sm + (it % 3) * G_STAGE;
        float* Hs = As + 64 * SA;
        #pragma unroll
        for (int kk = 0; kk < 32; kk += 8) {
            uint32_t a[2][4], bfr[4][2];
            #pragma unroll
            for (int t = 0; t < 2; t++) {
                int rb = R + t * 16 + ar;
                a[t][0] = __float_as_uint(As[rb * SA + kk + ac]);
                a[t][1] = __float_as_uint(As[(rb + 8) * SA + kk + ac]);
                a[t][2] = __float_as_uint(As[rb * SA + kk + ac + 4]);
                a[t][3] = __float_as_uint(As[(rb + 8) * SA + kk + ac + 4]);
            }
            #pragma unroll
            for (int n = 0; n < 4; n++) {
                int cb = C + n * 8 + ar;
                bfr[n][0] = __float_as_uint(Hs[(kk + ac) * SHS + cb]);
                bfr[n][1] = __float_as_uint(Hs[(kk + ac + 4) * SHS + cb]);
            }
            #pragma unroll
            for (int t = 0; t < 2; t++)
                #pragma unroll
                for (int n = 0; n < 4; n++)
                    mma_tf32(acc[t][n], a[t], bfr[n]);
        }
    }

    // direct float2 stores: row j, cols (i, i+1)
    #pragma unroll
    for (int t = 0; t < 2; t++) {
        #pragma unroll
        for (int n = 0; n < 4; n++) {
            int j = R + t * 16 + ar;
            int i = C + n * 8 + 2 * ac;
            float2 v0 = make_float2(acc[t][n][0], acc[t][n][1]);
            float2 v1 = make_float2(acc[t][n][2], acc[t][n][3]);
            *(float2*)&g_agg[(size_t)(b * NH + j) * HID + i0 + i]       = v0;
            *(float2*)&g_agg[(size_t)(b * NH + j + 8) * HID + i0 + i]   = v1;
        }
    }
}

// ---------------------------------------------------------------------------
// 6) g_mid[(b,n)][h*64+d] = agg[b][h*8+n][:] . Wv[h*64+d][:]
__global__ void k_mid(const float* __restrict__ Wv) {
    __shared__ float As[8][65];
    __shared__ float Bs[64][65];
    int h = blockIdx.x, b = blockIdx.y;
    int tid = threadIdx.x;
    float acc0 = 0.f, acc1 = 0.f;
    int o0 = tid, o1 = tid + 256;
    int n0 = o0 >> 6, d0 = o0 & 63;
    int n1 = o1 >> 6, d1 = o1 & 63;
    for (int kt = 0; kt < HID; kt += 64) {
        {
            int e = tid; int r = e >> 6, c = e & 63;
            As[r][c] = g_agg[(b * NH + h * SLOTS + r) * HID + kt + c];
            e = tid + 256; r = e >> 6; c = e & 63;
            As[r][c] = g_agg[(b * NH + h * SLOTS + r) * HID + kt + c];
        }
        #pragma unroll
        for (int l = 0; l < 16; l++) {
            int e = tid + l * 256;
            int r = e >> 6, c = e & 63;
            Bs[r][c] = Wv[(h * HD + r) * HID + kt + c];
        }
        __syncthreads();
        #pragma unroll
        for (int k = 0; k < 64; k++) {
            acc0 += As[n0][k] * Bs[d0][k];
            acc1 += As[n1][k] * Bs[d1][k];
        }
        __syncthreads();
    }
    g_mid[(b * SLOTS + n0) * BD + h * HD + d0] = acc0;
    g_mid[(b * SLOTS + n1) * BD + h * HD + d1] = acc1;
}

// ---------------------------------------------------------------------------
// 7) final[m=(b,n)][o] = g_mid[m][:] . Wo[o][:]   (32 x 4096, K=512)
__global__ void k_final(const float* __restrict__ Wo, float* __restrict__ out) {
    __shared__ float As[32][65];
    __shared__ float Bs[128][65];
    int tid = threadIdx.x;
    int tx = tid & 31, ty = tid >> 5;
    int o0 = blockIdx.x * 128;
    float acc[4][4] = {};
    for (int kt = 0; kt < BD; kt += 64) {
        #pragma unroll
        for (int l = 0; l < 8; l++) {
            int e = tid + l * 256;
            int r = e >> 6, c = e & 63;
            As[r][c] = g_mid[r * BD + kt + c];
        }
        #pragma unroll
        for (int l = 0; l < 32; l++) {
            int e = tid + l * 256;
            int r = e >> 6, c = e & 63;
            Bs[r][c] = Wo[(o0 + r) * BD + kt + c];
        }
        __syncthreads();
        #pragma unroll
        for (int k = 0; k < 64; k++) {
            float a[4], bb[4];
            #pragma unroll
            for (int x = 0; x < 4; x++) a[x] = As[ty * 4 + x][k];
            #pragma unroll
            for (int y = 0; y < 4; y++) bb[y] = Bs[tx * 4 + y][k];
            #pragma unroll
            for (int x = 0; x < 4; x++)
                #pragma unroll
                for (int y = 0; y < 4; y++) acc[x][y] += a[x] * bb[y];
        }
        __syncthreads();
    }
    #pragma unroll
    for (int x = 0; x < 4; x++)
        #pragma unroll
        for (int y = 0; y < 4; y++)
            out[(ty * 4 + x) * HID + o0 + tx * 4 + y] = acc[x][y];
}

// ---------------------------------------------------------------------------
extern "C" void kernel_launch(void* const* d_in, const int* in_sizes, int n_in,
                              void* d_out, int out_size) {
    const float* H    = (const float*)d_in[0];
    const int*   mask = (const int*)d_in[1];
    const float* ms   = (const float*)d_in[2];
    const float* Wq   = (const float*)d_in[3];
    const float* Wk   = (const float*)d_in[4];
    const float* Wv   = (const float*)d_in[5];
    const float* Wo   = (const float*)d_in[6];
    float* out = (float*)d_out;

    static int attr_done = 0;
    if (!attr_done) {
        cudaFuncSetAttribute(k_scores, cudaFuncAttributeMaxDynamicSharedMemorySize,
                             3 * S_STAGE * 4);
        cudaFuncSetAttribute(k_agg, cudaFuncAttributeMaxDynamicSharedMemorySize,
                             3 * G_STAGE * 4);
        attr_done = 1;
    }

    k_qproj <<<512, 256>>>(ms, Wq);
    k_qk    <<<dim3(HID / 256, NH), 256>>>(Wk);
    k_scores<<<(BB * SS) / 128, 256, 3 * S_STAGE * 4>>>(H);
    k_softmax<<<BB * NH, 256>>>(mask);
    k_agg   <<<dim3(HID / 128, BB), 256, 3 * G_STAGE * 4>>>(H);
    k_mid   <<<dim3(HEADS, BB), 256>>>(Wv);
    k_final <<<HID / 128, 256>>>(Wo, out);
}

// round 4
// speedup vs baseline: 2.5202x; 1.0651x over previous
#include <cuda_runtime.h>
#include <float.h>
#include <stdint.h>

#define HID 4096
#define SLOTS 8
#define HEADS 8
#define BD 512
#define HD 64
#define BB 4
#define SS 4096
#define NH 64   // HEADS*SLOTS

// Scratch (no allocations allowed)
__device__ float g_Q[SLOTS * BD];
__device__ float g_Qk[NH * HID];             // tf32-rounded, scaled by 1/8
__device__ float g_scores[BB * NH * SS];     // compacted scores -> attn in place
__device__ float g_agg[BB * NH * HID];
__device__ float g_mid[BB * SLOTS * BD];
__device__ int   g_sidx[BB * SS];            // compacted unmasked s indices
__device__ int   g_cnt[BB];                  // count of unmasked per batch

__device__ __forceinline__ uint32_t f2tf(float f) {
    uint32_t u;
    asm("cvt.rna.tf32.f32 %0, %1;" : "=r"(u) : "f"(f));
    return u;
}

__device__ __forceinline__ void mma_tf32(float* d, const uint32_t* a, const uint32_t* b) {
    asm volatile(
        "mma.sync.aligned.m16n8k8.row.col.f32.tf32.tf32.f32 "
        "{%0,%1,%2,%3}, {%4,%5,%6,%7}, {%8,%9}, {%0,%1,%2,%3};"
        : "+f"(d[0]), "+f"(d[1]), "+f"(d[2]), "+f"(d[3])
        : "r"(a[0]), "r"(a[1]), "r"(a[2]), "r"(a[3]), "r"(b[0]), "r"(b[1]));
}

__device__ __forceinline__ void cp16(uint32_t smem_dst, const float* gsrc) {
    asm volatile("cp.async.cg.shared.global [%0], [%1], 16;" :: "r"(smem_dst), "l"(gsrc));
}
#define CP_COMMIT asm volatile("cp.async.commit_group;")
#define CP_WAIT1  asm volatile("cp.async.wait_group 1;")

// ---------------------------------------------------------------------------
// 0) compaction: per batch, list of unmasked s (ascending) + count, padded w/ 0
__global__ void k_compact(const int* __restrict__ mask) {
    __shared__ int tsum[256];
    int b = blockIdx.x, tid = threadIdx.x;
    const int* m = mask + b * SS;
    int loc[16], cnt = 0;
    #pragma unroll
    for (int k = 0; k < 16; k++) {
        loc[k] = (m[tid * 16 + k] != 0);
        cnt += loc[k];
    }
    tsum[tid] = cnt;
    __syncthreads();
    for (int o = 1; o < 256; o <<= 1) {
        int v = (tid >= o) ? tsum[tid - o] : 0;
        __syncthreads();
        tsum[tid] += v;
        __syncthreads();
    }
    int off = tsum[tid] - cnt;
    int total = tsum[255];
    int* out = g_sidx + b * SS;
    #pragma unroll
    for (int k = 0; k < 16; k++)
        if (loc[k]) out[off++] = tid * 16 + k;
    if (tid == 0) {
        g_cnt[b] = total;
        int pad = (total + 31) & ~31;
        for (int i = total; i < pad + 32 && i < SS; i++) out[i] = 0;
    }
}

// ---------------------------------------------------------------------------
// 1) Q = memory_slots @ Wq^T   (8 x 512)
__global__ void k_qproj(const float* __restrict__ ms, const float* __restrict__ Wq) {
    int warp = (blockIdx.x * blockDim.x + threadIdx.x) >> 5;
    int lane = threadIdx.x & 31;
    if (warp >= SLOTS * BD) return;
    int n = warp / BD, c = warp % BD;
    const float* a = ms + n * HID;
    const float* w = Wq + c * HID;
    float acc = 0.f;
    for (int i = lane; i < HID; i += 32) acc += a[i] * w[i];
    #pragma unroll
    for (int off = 16; off; off >>= 1) acc += __shfl_down_sync(0xffffffffu, acc, off);
    if (lane == 0) g_Q[n * BD + c] = acc;
}

// ---------------------------------------------------------------------------
// 2) Qk[j][i] = (1/8) * sum_d Q[n][h*64+d] * Wk[h*64+d][i]  (tf32-rounded)
__global__ void k_qk(const float* __restrict__ Wk) {
    __shared__ float qs[HD];
    int j = blockIdx.y;
    int h = j >> 3, n = j & 7;
    if (threadIdx.x < HD) qs[threadIdx.x] = g_Q[n * BD + h * HD + threadIdx.x];
    __syncthreads();
    int i = blockIdx.x * blockDim.x + threadIdx.x;
    float acc = 0.f;
    #pragma unroll 8
    for (int d = 0; d < HD; d++) acc += qs[d] * Wk[(h * HD + d) * HID + i];
    g_Qk[j * HID + i] = __uint_as_float(f2tf(acc * 0.125f));
}

// ---------------------------------------------------------------------------
// 3) scores on compacted s-domain: C[cs][j] = H[sidx[cs],:] . Qk[j,:]
#define SA 36
#define S_STAGE (128 * SA + 64 * SA)
__global__ void k_scores(const float* __restrict__ H) {
    extern __shared__ float sm[];
    int b = blockIdx.y;
    int m0 = blockIdx.x * 128;
    int cnt = g_cnt[b];
    if (m0 >= cnt) return;
    int tid = threadIdx.x;
    int lane = tid & 31, w = tid >> 5;
    int wm = w & 3, wn = w >> 2;
    int R = wm * 32, C = wn * 32;
    int ar = lane >> 2, ac = lane & 3;

    uint32_t smem_u32 = (uint32_t)__cvta_generic_to_shared(sm);

    float acc[2][4][4];
    #pragma unroll
    for (int t = 0; t < 2; t++)
        #pragma unroll
        for (int n = 0; n < 4; n++)
            #pragma unroll
            for (int q = 0; q < 4; q++) acc[t][n][q] = 0.f;

    int lra = tid >> 3;
    int lca = (tid & 7) * 4;

    // gather row bases once (4 rows per thread)
    const float* rowp[4];
    #pragma unroll
    for (int p = 0; p < 4; p++) {
        int s = g_sidx[b * SS + m0 + p * 32 + lra];
        rowp[p] = H + ((size_t)b * SS + s) * HID + lca;
    }

    auto issue = [&](int stage, int kt) {
        uint32_t base = smem_u32 + stage * S_STAGE * 4;
        #pragma unroll
        for (int p = 0; p < 4; p++) {
            int r = p * 32 + lra;
            cp16(base + (r * SA + lca) * 4, rowp[p] + kt);
        }
        uint32_t bbase = base + 128 * SA * 4;
        #pragma unroll
        for (int p = 0; p < 2; p++) {
            int r = p * 32 + lra;
            cp16(bbase + (r * SA + lca) * 4, &g_Qk[r * HID + kt + lca]);
        }
    };

    issue(0, 0); CP_COMMIT;
    issue(1, 32); CP_COMMIT;

    const int NIT = HID / 32;
    for (int it = 0; it < NIT; it++) {
        CP_WAIT1;
        __syncthreads();
        if (it + 2 < NIT) issue((it + 2) % 3, (it + 2) * 32);
        CP_COMMIT;
        float* As = sm + (it % 3) * S_STAGE;
        float* Bs = As + 128 * SA;
        #pragma unroll
        for (int kk = 0; kk < 32; kk += 8) {
            uint32_t a[2][4], bfrag[4][2];
            #pragma unroll
            for (int t = 0; t < 2; t++) {
                int rb = R + t * 16 + ar;
                a[t][0] = __float_as_uint(As[rb * SA + kk + ac]);
                a[t][1] = __float_as_uint(As[(rb + 8) * SA + kk + ac]);
                a[t][2] = __float_as_uint(As[rb * SA + kk + ac + 4]);
                a[t][3] = __float_as_uint(As[(rb + 8) * SA + kk + ac + 4]);
            }
            #pragma unroll
            for (int n = 0; n < 4; n++) {
                int cb = C + n * 8 + ar;
                bfrag[n][0] = __float_as_uint(Bs[cb * SA + kk + ac]);
                bfrag[n][1] = __float_as_uint(Bs[cb * SA + kk + ac + 4]);
            }
            #pragma unroll
            for (int t = 0; t < 2; t++)
                #pragma unroll
                for (int n = 0; n < 4; n++)
                    mma_tf32(acc[t][n], a[t], bfrag[n]);
        }
    }
    __syncthreads();

    // transpose-stage C (128cs x 64j) -> g_scores[(b,j)][cs]
    float* Cs = sm;
    #pragma unroll
    for (int t = 0; t < 2; t++) {
        #pragma unroll
        for (int n = 0; n < 4; n++) {
            int row = R + t * 16 + ar;
            int col = C + n * 8 + 2 * ac;
            Cs[col * 130 + row]            = acc[t][n][0];
            Cs[(col + 1) * 130 + row]      = acc[t][n][1];
            Cs[col * 130 + row + 8]        = acc[t][n][2];
            Cs[(col + 1) * 130 + row + 8]  = acc[t][n][3];
        }
    }
    __syncthreads();
    #pragma unroll
    for (int l = 0; l < 32; l++) {
        int e = l * 256 + tid;
        int j = e >> 7, m = e & 127;
        g_scores[((b * NH + j) << 12) + m0 + m] = Cs[j * 130 + m];
    }
}

// ---------------------------------------------------------------------------
// 4) softmax over compacted prefix [0, cnt); zeros the padding
__global__ void k_softmax() {
    __shared__ float red[256];
    int row = blockIdx.x;            // b*NH + j
    int b = row >> 6;
    int cnt = g_cnt[b];
    float* sc = g_scores + row * SS;
    int tid = threadIdx.x;
    float v[16];
    float mx = -FLT_MAX;
    #pragma unroll
    for (int k = 0; k < 16; k++) {
        int s = k * 256 + tid;
        float val = (s < cnt) ? sc[s] : -FLT_MAX;
        v[k] = val;
        mx = fmaxf(mx, val);
    }
    red[tid] = mx; __syncthreads();
    for (int o = 128; o; o >>= 1) { if (tid < o) red[tid] = fmaxf(red[tid], red[tid + o]); __syncthreads(); }
    mx = red[0]; __syncthreads();
    float sum = 0.f;
    #pragma unroll
    for (int k = 0; k < 16; k++) { v[k] = __expf(v[k] - mx); sum += v[k]; }
    red[tid] = sum; __syncthreads();
    for (int o = 128; o; o >>= 1) { if (tid < o) red[tid] += red[tid + o]; __syncthreads(); }
    float inv = 1.f / red[0];
    #pragma unroll
    for (int k = 0; k < 16; k++) sc[k * 256 + tid] = __uint_as_float(f2tf(v[k] * inv));
}

// ---------------------------------------------------------------------------
// 5) agg on compacted s-domain with H row gather
#define SHS 136
#define G_STAGE (64 * SA + 32 * SHS)
__global__ void k_agg(const float* __restrict__ H) {
    extern __shared__ float sm[];
    int tid = threadIdx.x;
    int lane = tid & 31, w = tid >> 5;
    int wm = w >> 2, wn = w & 3;
    int R = wm * 32, C = wn * 32;
    int b = blockIdx.y;
    int i0 = blockIdx.x * 128;
    int ar = lane >> 2, ac = lane & 3;
    int cnt = g_cnt[b];
    int NIT = (cnt + 31) >> 5;

    uint32_t smem_u32 = (uint32_t)__cvta_generic_to_shared(sm);

    float acc[2][4][4];
    #pragma unroll
    for (int t = 0; t < 2; t++)
        #pragma unroll
        for (int n = 0; n < 4; n++)
            #pragma unroll
            for (int q = 0; q < 4; q++) acc[t][n][q] = 0.f;

    const float* Hb = H + (size_t)b * SS * HID;
    const float* A  = g_scores + b * NH * SS;
    const int* sidx = g_sidx + b * SS;

    int lra = tid >> 3;
    int lca = (tid & 7) * 4;
    int hr = tid >> 5;           // uniform per warp
    int hc = (tid & 31) * 4;

    auto issue = [&](int stage, int st) {
        uint32_t base = smem_u32 + stage * G_STAGE * 4;
        #pragma unroll
        for (int p = 0; p < 2; p++) {
            int r = p * 32 + lra;
            cp16(base + (r * SA + lca) * 4, &A[r * SS + st + lca]);
        }
        uint32_t hbase = base + 64 * SA * 4;
        #pragma unroll
        for (int p = 0; p < 4; p++) {
            int r = p * 8 + hr;
            int gi = sidx[st + r];
            cp16(hbase + (r * SHS + hc) * 4, &Hb[(size_t)gi * HID + i0 + hc]);
        }
    };

    if (NIT > 0) {
        issue(0, 0); CP_COMMIT;
        issue(1, 32); CP_COMMIT;
        for (int it = 0; it < NIT; it++) {
            CP_WAIT1;
            __syncthreads();
            if (it + 2 < NIT) issue((it + 2) % 3, (it + 2) * 32);
            CP_COMMIT;
            float* As = sm + (it % 3) * G_STAGE;
            float* Hs = As + 64 * SA;
            #pragma unroll
            for (int kk = 0; kk < 32; kk += 8) {
                uint32_t a[2][4], bfr[4][2];
                #pragma unroll
                for (int t = 0; t < 2; t++) {
                    int rb = R + t * 16 + ar;
                    a[t][0] = __float_as_uint(As[rb * SA + kk + ac]);
                    a[t][1] = __float_as_uint(As[(rb + 8) * SA + kk + ac]);
                    a[t][2] = __float_as_uint(As[rb * SA + kk + ac + 4]);
                    a[t][3] = __float_as_uint(As[(rb + 8) * SA + kk + ac + 4]);
                }
                #pragma unroll
                for (int n = 0; n < 4; n++) {
                    int cb = C + n * 8 + ar;
                    bfr[n][0] = __float_as_uint(Hs[(kk + ac) * SHS + cb]);
                    bfr[n][1] = __float_as_uint(Hs[(kk + ac + 4) * SHS + cb]);
                }
                #pragma unroll
                for (int t = 0; t < 2; t++)
                    #pragma unroll
                    for (int n = 0; n < 4; n++)
                        mma_tf32(acc[t][n], a[t], bfr[n]);
            }
        }
    }

    #pragma unroll
    for (int t = 0; t < 2; t++) {
        #pragma unroll
        for (int n = 0; n < 4; n++) {
            int j = R + t * 16 + ar;
            int i = C + n * 8 + 2 * ac;
            float2 v0 = make_float2(acc[t][n][0], acc[t][n][1]);
            float2 v1 = make_float2(acc[t][n][2], acc[t][n][3]);
            *(float2*)&g_agg[(size_t)(b * NH + j) * HID + i0 + i]       = v0;
            *(float2*)&g_agg[(size_t)(b * NH + j + 8) * HID + i0 + i]   = v1;
        }
    }
}

// ---------------------------------------------------------------------------
// 6) g_mid[(b,n)][h*64+d] = agg[b][h*8+n][:] . Wv[h*64+d][:]
__global__ void k_mid(const float* __restrict__ Wv) {
    __shared__ float As[8][65];
    __shared__ float Bs[64][65];
    int h = blockIdx.x, b = blockIdx.y;
    int tid = threadIdx.x;
    float acc0 = 0.f, acc1 = 0.f;
    int o0 = tid, o1 = tid + 256;
    int n0 = o0 >> 6, d0 = o0 & 63;
    int n1 = o1 >> 6, d1 = o1 & 63;
    for (int kt = 0; kt < HID; kt += 64) {
        {
            int e = tid; int r = e >> 6, c = e & 63;
            As[r][c] = g_agg[(b * NH + h * SLOTS + r) * HID + kt + c];
            e = tid + 256; r = e >> 6; c = e & 63;
            As[r][c] = g_agg[(b * NH + h * SLOTS + r) * HID + kt + c];
        }
        #pragma unroll
        for (int l = 0; l < 16; l++) {
            int e = tid + l * 256;
            int r = e >> 6, c = e & 63;
            Bs[r][c] = Wv[(h * HD + r) * HID + kt + c];
        }
        __syncthreads();
        #pragma unroll
        for (int k = 0; k < 64; k++) {
            acc0 += As[n0][k] * Bs[d0][k];
            acc1 += As[n1][k] * Bs[d1][k];
        }
        __syncthreads();
    }
    g_mid[(b * SLOTS + n0) * BD + h * HD + d0] = acc0;
    g_mid[(b * SLOTS + n1) * BD + h * HD + d1] = acc1;
}

// ---------------------------------------------------------------------------
// 7) final[m=(b,n)][o] = g_mid[m][:] . Wo[o][:]
__global__ void k_final(const float* __restrict__ Wo, float* __restrict__ out) {
    __shared__ float As[32][65];
    __shared__ float Bs[128][65];
    int tid = threadIdx.x;
    int tx = tid & 31, ty = tid >> 5;
    int o0 = blockIdx.x * 128;
    float acc[4][4] = {};
    for (int kt = 0; kt < BD; kt += 64) {
        #pragma unroll
        for (int l = 0; l < 8; l++) {
            int e = tid + l * 256;
            int r = e >> 6, c = e & 63;
            As[r][c] = g_mid[r * BD + kt + c];
        }
        #pragma unroll
        for (int l = 0; l < 32; l++) {
            int e = tid + l * 256;
            int r = e >> 6, c = e & 63;
            Bs[r][c] = Wo[(o0 + r) * BD + kt + c];
        }
        __syncthreads();
        #pragma unroll
        for (int k = 0; k < 64; k++) {
            float a[4], bb[4];
            #pragma unroll
            for (int x = 0; x < 4; x++) a[x] = As[ty * 4 + x][k];
            #pragma unroll
            for (int y = 0; y < 4; y++) bb[y] = Bs[tx * 4 + y][k];
            #pragma unroll
            for (int x = 0; x < 4; x++)
                #pragma unroll
                for (int y = 0; y < 4; y++) acc[x][y] += a[x] * bb[y];
        }
        __syncthreads();
    }
    #pragma unroll
    for (int x = 0; x < 4; x++)
        #pragma unroll
        for (int y = 0; y < 4; y++)
            out[(ty * 4 + x) * HID + o0 + tx * 4 + y] = acc[x][y];
}

// ---------------------------------------------------------------------------
extern "C" void kernel_launch(void* const* d_in, const int* in_sizes, int n_in,
                              void* d_out, int out_size) {
    const float* H    = (const float*)d_in[0];
    const int*   mask = (const int*)d_in[1];
    const float* ms   = (const float*)d_in[2];
    const float* Wq   = (const float*)d_in[3];
    const float* Wk   = (const float*)d_in[4];
    const float* Wv   = (const float*)d_in[5];
    const float* Wo   = (const float*)d_in[6];
    float* out = (float*)d_out;

    static int attr_done = 0;
    if (!attr_done) {
        cudaFuncSetAttribute(k_scores, cudaFuncAttributeMaxDynamicSharedMemorySize,
                             3 * S_STAGE * 4);
        cudaFuncSetAttribute(k_agg, cudaFuncAttributeMaxDynamicSharedMemorySize,
                             3 * G_STAGE * 4);
        attr_done = 1;
    }

    k_compact<<<BB, 256>>>(mask);
    k_qproj <<<512, 256>>>(ms, Wq);
    k_qk    <<<dim3(HID / 256, NH), 256>>>(Wk);
    k_scores<<<dim3(SS / 128, BB), 256, 3 * S_STAGE * 4>>>(H);
    k_softmax<<<BB * NH, 256>>>();
    k_agg   <<<dim3(HID / 128, BB), 256, 3 * G_STAGE * 4>>>(H);
    k_mid   <<<dim3(HEADS, BB), 256>>>(Wv);
    k_final <<<HID / 128, 256>>>(Wo, out);
}

// round 5
// speedup vs baseline: 3.8583x; 1.5309x over previous
#include <cuda_runtime.h>
#include <float.h>
#include <stdint.h>

#define HID 4096
#define SLOTS 8
#define HEADS 8
#define BD 512
#define HD 64
#define BB 4
#define SS 4096
#define NH 64   // HEADS*SLOTS

// Scratch (no allocations allowed)
__device__ float g_Q[SLOTS * BD];
__device__ float g_Qk[NH * HID];             // tf32-rounded, scaled by 1/8
__device__ float g_scores[BB * NH * SS];     // compacted scores -> attn in place
__device__ float g_agg[BB * NH * HID];
__device__ float g_mid[BB * SLOTS * BD];
__device__ int   g_sidx[BB * SS];
__device__ int   g_cnt[BB];

__device__ __forceinline__ uint32_t f2tf(float f) {
    uint32_t u;
    asm("cvt.rna.tf32.f32 %0, %1;" : "=r"(u) : "f"(f));
    return u;
}

__device__ __forceinline__ void mma_tf32(float* d, const uint32_t* a, const uint32_t* b) {
    asm volatile(
        "mma.sync.aligned.m16n8k8.row.col.f32.tf32.tf32.f32 "
        "{%0,%1,%2,%3}, {%4,%5,%6,%7}, {%8,%9}, {%0,%1,%2,%3};"
        : "+f"(d[0]), "+f"(d[1]), "+f"(d[2]), "+f"(d[3])
        : "r"(a[0]), "r"(a[1]), "r"(a[2]), "r"(a[3]), "r"(b[0]), "r"(b[1]));
}

__device__ __forceinline__ void cp16(uint32_t smem_dst, const float* gsrc) {
    asm volatile("cp.async.cg.shared.global [%0], [%1], 16;" :: "r"(smem_dst), "l"(gsrc));
}
#define CP_COMMIT asm volatile("cp.async.commit_group;")
#define CP_WAIT1  asm volatile("cp.async.wait_group 1;")

// ---------------------------------------------------------------------------
// 0) compaction + zero g_mid
__global__ void k_compact(const int* __restrict__ mask) {
    __shared__ int tsum[256];
    int b = blockIdx.x, tid = threadIdx.x;
    const int* m = mask + b * SS;
    int loc[16], cnt = 0;
    #pragma unroll
    for (int k = 0; k < 16; k++) {
        loc[k] = (m[tid * 16 + k] != 0);
        cnt += loc[k];
    }
    tsum[tid] = cnt;
    __syncthreads();
    for (int o = 1; o < 256; o <<= 1) {
        int v = (tid >= o) ? tsum[tid - o] : 0;
        __syncthreads();
        tsum[tid] += v;
        __syncthreads();
    }
    int off = tsum[tid] - cnt;
    int total = tsum[255];
    int* out = g_sidx + b * SS;
    #pragma unroll
    for (int k = 0; k < 16; k++)
        if (loc[k]) out[off++] = tid * 16 + k;
    if (tid == 0) {
        g_cnt[b] = total;
        int pad = (total + 31) & ~31;
        for (int i = total; i < pad + 32 && i < SS; i++) out[i] = 0;
    }
    // zero g_mid (16384 floats total; 4096 per block)
    float* gm = g_mid + b * 4096;
    #pragma unroll
    for (int k = 0; k < 16; k++) gm[k * 256 + tid] = 0.f;
}

// ---------------------------------------------------------------------------
// 1) Q = memory_slots @ Wq^T
__global__ void k_qproj(const float* __restrict__ ms, const float* __restrict__ Wq) {
    int warp = (blockIdx.x * blockDim.x + threadIdx.x) >> 5;
    int lane = threadIdx.x & 31;
    if (warp >= SLOTS * BD) return;
    int n = warp / BD, c = warp % BD;
    const float* a = ms + n * HID;
    const float* w = Wq + c * HID;
    float acc = 0.f;
    for (int i = lane; i < HID; i += 32) acc += a[i] * w[i];
    #pragma unroll
    for (int off = 16; off; off >>= 1) acc += __shfl_down_sync(0xffffffffu, acc, off);
    if (lane == 0) g_Q[n * BD + c] = acc;
}

// ---------------------------------------------------------------------------
// 2) Qk (tf32-rounded, /8)
__global__ void k_qk(const float* __restrict__ Wk) {
    __shared__ float qs[HD];
    int j = blockIdx.y;
    int h = j >> 3, n = j & 7;
    if (threadIdx.x < HD) qs[threadIdx.x] = g_Q[n * BD + h * HD + threadIdx.x];
    __syncthreads();
    int i = blockIdx.x * blockDim.x + threadIdx.x;
    float acc = 0.f;
    #pragma unroll 8
    for (int d = 0; d < HD; d++) acc += qs[d] * Wk[(h * HD + d) * HID + i];
    g_Qk[j * HID + i] = __uint_as_float(f2tf(acc * 0.125f));
}

// ---------------------------------------------------------------------------
// 3) scores, CTA tile 64cs x 64j, 3-stage cp.async, 4 CTAs/SM
#define SA 36
#define S_STAGE (128 * SA)    // 64 A rows + 64 B rows
__global__ void k_scores(const float* __restrict__ H) {
    extern __shared__ float sm[];
    int b = blockIdx.y;
    int m0 = blockIdx.x * 64;
    int cnt = g_cnt[b];
    if (m0 >= cnt) return;
    int tid = threadIdx.x;
    int lane = tid & 31, w = tid >> 5;
    int wm = w & 1, wn = w >> 1;     // 2 m-tiles x 4 j-tiles
    int R = wm * 32, C = wn * 16;
    int ar = lane >> 2, ac = lane & 3;

    uint32_t smem_u32 = (uint32_t)__cvta_generic_to_shared(sm);

    float acc[2][2][4];
    #pragma unroll
    for (int t = 0; t < 2; t++)
        #pragma unroll
        for (int n = 0; n < 2; n++)
            #pragma unroll
            for (int q = 0; q < 4; q++) acc[t][n][q] = 0.f;

    int lra = tid >> 3;              // 0..31
    int lca = (tid & 7) * 4;

    const float* rowp[2];
    #pragma unroll
    for (int p = 0; p < 2; p++) {
        int s = g_sidx[b * SS + m0 + p * 32 + lra];
        rowp[p] = H + ((size_t)b * SS + s) * HID + lca;
    }

    auto issue = [&](int stage, int kt) {
        uint32_t base = smem_u32 + stage * S_STAGE * 4;
        #pragma unroll
        for (int p = 0; p < 2; p++) {
            int r = p * 32 + lra;
            cp16(base + (r * SA + lca) * 4, rowp[p] + kt);
        }
        uint32_t bbase = base + 64 * SA * 4;
        #pragma unroll
        for (int p = 0; p < 2; p++) {
            int r = p * 32 + lra;
            cp16(bbase + (r * SA + lca) * 4, &g_Qk[r * HID + kt + lca]);
        }
    };

    issue(0, 0); CP_COMMIT;
    issue(1, 32); CP_COMMIT;

    const int NIT = HID / 32;
    for (int it = 0; it < NIT; it++) {
        CP_WAIT1;
        __syncthreads();
        if (it + 2 < NIT) issue((it + 2) % 3, (it + 2) * 32);
        CP_COMMIT;
        float* As = sm + (it % 3) * S_STAGE;
        float* Bs = As + 64 * SA;
        #pragma unroll
        for (int kk = 0; kk < 32; kk += 8) {
            uint32_t a[2][4], bfrag[2][2];
            #pragma unroll
            for (int t = 0; t < 2; t++) {
                int rb = R + t * 16 + ar;
                a[t][0] = __float_as_uint(As[rb * SA + kk + ac]);
                a[t][1] = __float_as_uint(As[(rb + 8) * SA + kk + ac]);
                a[t][2] = __float_as_uint(As[rb * SA + kk + ac + 4]);
                a[t][3] = __float_as_uint(As[(rb + 8) * SA + kk + ac + 4]);
            }
            #pragma unroll
            for (int n = 0; n < 2; n++) {
                int cb = C + n * 8 + ar;
                bfrag[n][0] = __float_as_uint(Bs[cb * SA + kk + ac]);
                bfrag[n][1] = __float_as_uint(Bs[cb * SA + kk + ac + 4]);
            }
            #pragma unroll
            for (int t = 0; t < 2; t++)
                #pragma unroll
                for (int n = 0; n < 2; n++)
                    mma_tf32(acc[t][n], a[t], bfrag[n]);
        }
    }
    __syncthreads();

    // transpose-stage C (64cs x 64j) -> g_scores[(b,j)][cs]
    float* Cs = sm;
    #pragma unroll
    for (int t = 0; t < 2; t++) {
        #pragma unroll
        for (int n = 0; n < 2; n++) {
            int row = R + t * 16 + ar;
            int col = C + n * 8 + 2 * ac;
            Cs[col * 65 + row]            = acc[t][n][0];
            Cs[(col + 1) * 65 + row]      = acc[t][n][1];
            Cs[col * 65 + row + 8]        = acc[t][n][2];
            Cs[(col + 1) * 65 + row + 8]  = acc[t][n][3];
        }
    }
    __syncthreads();
    #pragma unroll
    for (int l = 0; l < 16; l++) {
        int e = l * 256 + tid;
        int j = e >> 6, m = e & 63;
        g_scores[((b * NH + j) << 12) + m0 + m] = Cs[j * 65 + m];
    }
}

// ---------------------------------------------------------------------------
// 4) softmax over compacted prefix
__global__ void k_softmax() {
    __shared__ float red[256];
    int row = blockIdx.x;
    int b = row >> 6;
    int cnt = g_cnt[b];
    float* sc = g_scores + row * SS;
    int tid = threadIdx.x;
    float v[16];
    float mx = -FLT_MAX;
    #pragma unroll
    for (int k = 0; k < 16; k++) {
        int s = k * 256 + tid;
        float val = (s < cnt) ? sc[s] : -FLT_MAX;
        v[k] = val;
        mx = fmaxf(mx, val);
    }
    red[tid] = mx; __syncthreads();
    for (int o = 128; o; o >>= 1) { if (tid < o) red[tid] = fmaxf(red[tid], red[tid + o]); __syncthreads(); }
    mx = red[0]; __syncthreads();
    float sum = 0.f;
    #pragma unroll
    for (int k = 0; k < 16; k++) { v[k] = __expf(v[k] - mx); sum += v[k]; }
    red[tid] = sum; __syncthreads();
    for (int o = 128; o; o >>= 1) { if (tid < o) red[tid] += red[tid + o]; __syncthreads(); }
    float inv = 1.f / red[0];
    #pragma unroll
    for (int k = 0; k < 16; k++) sc[k * 256 + tid] = __uint_as_float(f2tf(v[k] * inv));
}

// ---------------------------------------------------------------------------
// 5) agg, CTA tile 64j x 64i, 3-stage cp.async, 4 CTAs/SM
#define SHS 72
#define G_STAGE (64 * SA + 32 * SHS)   // 4608 floats
__global__ void k_agg(const float* __restrict__ H) {
    extern __shared__ float sm[];
    int tid = threadIdx.x;
    int lane = tid & 31, w = tid >> 5;
    int wm = w & 1, wn = w >> 1;       // 2 j-tiles x 4 i-tiles
    int R = wm * 32, C = wn * 16;
    int b = blockIdx.y;
    int i0 = blockIdx.x * 64;
    int ar = lane >> 2, ac = lane & 3;
    int cnt = g_cnt[b];
    int NIT = (cnt + 31) >> 5;

    uint32_t smem_u32 = (uint32_t)__cvta_generic_to_shared(sm);

    float acc[2][2][4];
    #pragma unroll
    for (int t = 0; t < 2; t++)
        #pragma unroll
        for (int n = 0; n < 2; n++)
            #pragma unroll
            for (int q = 0; q < 4; q++) acc[t][n][q] = 0.f;

    const float* Hb = H + (size_t)b * SS * HID;
    const float* A  = g_scores + b * NH * SS;
    const int* sidx = g_sidx + b * SS;

    int lra = tid >> 3;              // 0..31
    int lca = (tid & 7) * 4;
    int hr = tid >> 4;               // 0..15
    int hc = (tid & 15) * 4;

    auto issue = [&](int stage, int st) {
        uint32_t base = smem_u32 + stage * G_STAGE * 4;
        #pragma unroll
        for (int p = 0; p < 2; p++) {
            int r = p * 32 + lra;
            cp16(base + (r * SA + lca) * 4, &A[r * SS + st + lca]);
        }
        uint32_t hbase = base + 64 * SA * 4;
        #pragma unroll
        for (int p = 0; p < 2; p++) {
            int r = p * 16 + hr;
            int gi = sidx[st + r];
            cp16(hbase + (r * SHS + hc) * 4, &Hb[(size_t)gi * HID + i0 + hc]);
        }
    };

    if (NIT > 0) {
        issue(0, 0); CP_COMMIT;
        issue(1, 32); CP_COMMIT;
        for (int it = 0; it < NIT; it++) {
            CP_WAIT1;
            __syncthreads();
            if (it + 2 < NIT) issue((it + 2) % 3, (it + 2) * 32);
            CP_COMMIT;
            float* As = sm + (it % 3) * G_STAGE;
            float* Hs = As + 64 * SA;
            #pragma unroll
            for (int kk = 0; kk < 32; kk += 8) {
                uint32_t a[2][4], bfr[2][2];
                #pragma unroll
                for (int t = 0; t < 2; t++) {
                    int rb = R + t * 16 + ar;
                    a[t][0] = __float_as_uint(As[rb * SA + kk + ac]);
                    a[t][1] = __float_as_uint(As[(rb + 8) * SA + kk + ac]);
                    a[t][2] = __float_as_uint(As[rb * SA + kk + ac + 4]);
                    a[t][3] = __float_as_uint(As[(rb + 8) * SA + kk + ac + 4]);
                }
                #pragma unroll
                for (int n = 0; n < 2; n++) {
                    int cb = C + n * 8 + ar;
                    bfr[n][0] = __float_as_uint(Hs[(kk + ac) * SHS + cb]);
                    bfr[n][1] = __float_as_uint(Hs[(kk + ac + 4) * SHS + cb]);
                }
                #pragma unroll
                for (int t = 0; t < 2; t++)
                    #pragma unroll
                    for (int n = 0; n < 2; n++)
                        mma_tf32(acc[t][n], a[t], bfr[n]);
            }
        }
    }

    #pragma unroll
    for (int t = 0; t < 2; t++) {
        #pragma unroll
        for (int n = 0; n < 2; n++) {
            int j = R + t * 16 + ar;
            int i = C + n * 8 + 2 * ac;
            float2 v0 = make_float2(acc[t][n][0], acc[t][n][1]);
            float2 v1 = make_float2(acc[t][n][2], acc[t][n][3]);
            *(float2*)&g_agg[(size_t)(b * NH + j) * HID + i0 + i]     = v0;
            *(float2*)&g_agg[(size_t)(b * NH + j + 8) * HID + i0 + i] = v1;
        }
    }
}

// ---------------------------------------------------------------------------
// 6) mid, split-K x4 with atomic epilogue
__global__ void k_mid(const float* __restrict__ Wv) {
    __shared__ float As[8][65];
    __shared__ float Bs[64][65];
    int h = blockIdx.x, b = blockIdx.y, kc = blockIdx.z;
    int tid = threadIdx.x;
    float acc0 = 0.f, acc1 = 0.f;
    int o0 = tid, o1 = tid + 256;
    int n0 = o0 >> 6, d0 = o0 & 63;
    int n1 = o1 >> 6, d1 = o1 & 63;
    int k0 = kc * (HID / 4), k1 = k0 + HID / 4;
    for (int kt = k0; kt < k1; kt += 64) {
        {
            int e = tid; int r = e >> 6, c = e & 63;
            As[r][c] = g_agg[(b * NH + h * SLOTS + r) * HID + kt + c];
            e = tid + 256; r = e >> 6; c = e & 63;
            As[r][c] = g_agg[(b * NH + h * SLOTS + r) * HID + kt + c];
        }
        #pragma unroll
        for (int l = 0; l < 16; l++) {
            int e = tid + l * 256;
            int r = e >> 6, c = e & 63;
            Bs[r][c] = Wv[(h * HD + r) * HID + kt + c];
        }
        __syncthreads();
        #pragma unroll
        for (int k = 0; k < 64; k++) {
            acc0 += As[n0][k] * Bs[d0][k];
            acc1 += As[n1][k] * Bs[d1][k];
        }
        __syncthreads();
    }
    atomicAdd(&g_mid[(b * SLOTS + n0) * BD + h * HD + d0], acc0);
    atomicAdd(&g_mid[(b * SLOTS + n1) * BD + h * HD + d1], acc1);
}

// ---------------------------------------------------------------------------
// 7) final, o-tile 64 (grid 64)
__global__ void k_final(const float* __restrict__ Wo, float* __restrict__ out) {
    __shared__ float As[32][65];
    __shared__ float Bs[64][65];
    int tid = threadIdx.x;
    int tx = tid & 15, ty = tid >> 4;
    int o0 = blockIdx.x * 64;
    float acc[2][4] = {};
    for (int kt = 0; kt < BD; kt += 64) {
        #pragma unroll
        for (int l = 0; l < 8; l++) {
            int e = tid + l * 256;
            int r = e >> 6, c = e & 63;
            As[r][c] = g_mid[r * BD + kt + c];
        }
        #pragma unroll
        for (int l = 0; l < 16; l++) {
            int e = tid + l * 256;
            int r = e >> 6, c = e & 63;
            Bs[r][c] = Wo[(o0 + r) * BD + kt + c];
        }
        __syncthreads();
        #pragma unroll
        for (int k = 0; k < 64; k++) {
            float a[2], bb[4];
            #pragma unroll
            for (int x = 0; x < 2; x++) a[x] = As[ty * 2 + x][k];
            #pragma unroll
            for (int y = 0; y < 4; y++) bb[y] = Bs[tx * 4 + y][k];
            #pragma unroll
            for (int x = 0; x < 2; x++)
                #pragma unroll
                for (int y = 0; y < 4; y++) acc[x][y] += a[x] * bb[y];
        }
        __syncthreads();
    }
    #pragma unroll
    for (int x = 0; x < 2; x++)
        #pragma unroll
        for (int y = 0; y < 4; y++)
            out[(ty * 2 + x) * HID + o0 + tx * 4 + y] = acc[x][y];
}

// ---------------------------------------------------------------------------
extern "C" void kernel_launch(void* const* d_in, const int* in_sizes, int n_in,
                              void* d_out, int out_size) {
    const float* H    = (const float*)d_in[0];
    const int*   mask = (const int*)d_in[1];
    const float* ms   = (const float*)d_in[2];
    const float* Wq   = (const float*)d_in[3];
    const float* Wk   = (const float*)d_in[4];
    const float* Wv   = (const float*)d_in[5];
    const float* Wo   = (const float*)d_in[6];
    float* out = (float*)d_out;

    static int attr_done = 0;
    if (!attr_done) {
        cudaFuncSetAttribute(k_scores, cudaFuncAttributeMaxDynamicSharedMemorySize,
                             3 * S_STAGE * 4);
        cudaFuncSetAttribute(k_agg, cudaFuncAttributeMaxDynamicSharedMemorySize,
                             3 * G_STAGE * 4);
        attr_done = 1;
    }

    k_compact<<<BB, 256>>>(mask);
    k_qproj <<<512, 256>>>(ms, Wq);
    k_qk    <<<dim3(HID / 256, NH), 256>>>(Wk);
    k_scores<<<dim3(SS / 64, BB), 256, 3 * S_STAGE * 4>>>(H);
    k_softmax<<<BB * NH, 256>>>();
    k_agg   <<<dim3(HID / 64, BB), 256, 3 * G_STAGE * 4>>>(H);
    k_mid   <<<dim3(HEADS, BB, 4), 256>>>(Wv);
    k_final <<<HID / 64, 256>>>(Wo, out);
}

// round 6
// speedup vs baseline: 4.1534x; 1.0765x over previous
#include <cuda_runtime.h>
#include <float.h>
#include <stdint.h>

#define HID 4096
#define SLOTS 8
#define HEADS 8
#define BD 512
#define HD 64
#define BB 4
#define SS 4096
#define NH 64   // HEADS*SLOTS

// Scratch (no allocations allowed)
__device__ float g_Q[SLOTS * BD];
__device__ float g_Qk[NH * HID];                 // tf32-rounded, scaled by 1/8
__device__ float g_spart[4 * BB * NH * SS];      // 16 MB split-K score partials
__device__ float g_scores[BB * NH * SS];         // attn probs
__device__ float g_apart[2 * BB * NH * HID];     // 8 MB split-s agg partials
__device__ float g_mid[BB * SLOTS * BD];
__device__ int   g_sidx[BB * SS];
__device__ int   g_cnt[BB];

#define SPART_SZ (BB * NH * SS)
#define APART_SZ (BB * NH * HID)

__device__ __forceinline__ uint32_t f2tf(float f) {
    uint32_t u;
    asm("cvt.rna.tf32.f32 %0, %1;" : "=r"(u) : "f"(f));
    return u;
}

__device__ __forceinline__ void mma_tf32(float* d, const uint32_t* a, const uint32_t* b) {
    asm volatile(
        "mma.sync.aligned.m16n8k8.row.col.f32.tf32.tf32.f32 "
        "{%0,%1,%2,%3}, {%4,%5,%6,%7}, {%8,%9}, {%0,%1,%2,%3};"
        : "+f"(d[0]), "+f"(d[1]), "+f"(d[2]), "+f"(d[3])
        : "r"(a[0]), "r"(a[1]), "r"(a[2]), "r"(a[3]), "r"(b[0]), "r"(b[1]));
}

__device__ __forceinline__ void cp16(uint32_t smem_dst, const float* gsrc) {
    asm volatile("cp.async.cg.shared.global [%0], [%1], 16;" :: "r"(smem_dst), "l"(gsrc));
}
#define CP_COMMIT asm volatile("cp.async.commit_group;")
#define CP_WAIT1  asm volatile("cp.async.wait_group 1;")

// ---------------------------------------------------------------------------
// 0) compaction + zero g_mid
__global__ void k_compact(const int* __restrict__ mask) {
    __shared__ int tsum[256];
    int b = blockIdx.x, tid = threadIdx.x;
    const int* m = mask + b * SS;
    int loc[16], cnt = 0;
    #pragma unroll
    for (int k = 0; k < 16; k++) {
        loc[k] = (m[tid * 16 + k] != 0);
        cnt += loc[k];
    }
    tsum[tid] = cnt;
    __syncthreads();
    for (int o = 1; o < 256; o <<= 1) {
        int v = (tid >= o) ? tsum[tid - o] : 0;
        __syncthreads();
        tsum[tid] += v;
        __syncthreads();
    }
    int off = tsum[tid] - cnt;
    int total = tsum[255];
    int* out = g_sidx + b * SS;
    #pragma unroll
    for (int k = 0; k < 16; k++)
        if (loc[k]) out[off++] = tid * 16 + k;
    if (tid == 0) {
        g_cnt[b] = total;
        int pad = (total + 31) & ~31;
        for (int i = total; i < pad + 32 && i < SS; i++) out[i] = 0;
    }
    float* gm = g_mid + b * 4096;
    #pragma unroll
    for (int k = 0; k < 16; k++) gm[k * 256 + tid] = 0.f;
}

// ---------------------------------------------------------------------------
// 1) Q = memory_slots @ Wq^T
__global__ void k_qproj(const float* __restrict__ ms, const float* __restrict__ Wq) {
    int warp = (blockIdx.x * blockDim.x + threadIdx.x) >> 5;
    int lane = threadIdx.x & 31;
    if (warp >= SLOTS * BD) return;
    int n = warp / BD, c = warp % BD;
    const float* a = ms + n * HID;
    const float* w = Wq + c * HID;
    float acc = 0.f;
    for (int i = lane; i < HID; i += 32) acc += a[i] * w[i];
    #pragma unroll
    for (int off = 16; off; off >>= 1) acc += __shfl_down_sync(0xffffffffu, acc, off);
    if (lane == 0) g_Q[n * BD + c] = acc;
}

// ---------------------------------------------------------------------------
// 2) Qk (tf32-rounded, /8)
__global__ void k_qk(const float* __restrict__ Wk) {
    __shared__ float qs[HD];
    int j = blockIdx.y;
    int h = j >> 3, n = j & 7;
    if (threadIdx.x < HD) qs[threadIdx.x] = g_Q[n * BD + h * HD + threadIdx.x];
    __syncthreads();
    int i = blockIdx.x * blockDim.x + threadIdx.x;
    float acc = 0.f;
    #pragma unroll 8
    for (int d = 0; d < HD; d++) acc += qs[d] * Wk[(h * HD + d) * HID + i];
    g_Qk[j * HID + i] = __uint_as_float(f2tf(acc * 0.125f));
}

// ---------------------------------------------------------------------------
// 3) scores: CTA tile 64cs x 64j, split-K x4, 3-stage cp.async
#define SA 36
#define S_STAGE (128 * SA)
__global__ void k_scores(const float* __restrict__ H) {
    extern __shared__ float sm[];
    int b = blockIdx.y;
    int m0 = blockIdx.x * 64;
    int kc = blockIdx.z;
    int cnt = g_cnt[b];
    if (m0 >= cnt) return;
    int tid = threadIdx.x;
    int lane = tid & 31, w = tid >> 5;
    int wm = w & 1, wn = w >> 1;
    int R = wm * 32, C = wn * 16;
    int ar = lane >> 2, ac = lane & 3;

    uint32_t smem_u32 = (uint32_t)__cvta_generic_to_shared(sm);

    float acc[2][2][4];
    #pragma unroll
    for (int t = 0; t < 2; t++)
        #pragma unroll
        for (int n = 0; n < 2; n++)
            #pragma unroll
            for (int q = 0; q < 4; q++) acc[t][n][q] = 0.f;

    int lra = tid >> 3;
    int lca = (tid & 7) * 4;
    int kbase = kc * (HID / 4);

    const float* rowp[2];
    #pragma unroll
    for (int p = 0; p < 2; p++) {
        int s = g_sidx[b * SS + m0 + p * 32 + lra];
        rowp[p] = H + ((size_t)b * SS + s) * HID + kbase + lca;
    }

    auto issue = [&](int stage, int kt) {
        uint32_t base = smem_u32 + stage * S_STAGE * 4;
        #pragma unroll
        for (int p = 0; p < 2; p++) {
            int r = p * 32 + lra;
            cp16(base + (r * SA + lca) * 4, rowp[p] + kt);
        }
        uint32_t bbase = base + 64 * SA * 4;
        #pragma unroll
        for (int p = 0; p < 2; p++) {
            int r = p * 32 + lra;
            cp16(bbase + (r * SA + lca) * 4, &g_Qk[r * HID + kbase + kt + lca]);
        }
    };

    issue(0, 0); CP_COMMIT;
    issue(1, 32); CP_COMMIT;

    const int NIT = HID / 4 / 32;   // 32
    for (int it = 0; it < NIT; it++) {
        CP_WAIT1;
        __syncthreads();
        if (it + 2 < NIT) issue((it + 2) % 3, (it + 2) * 32);
        CP_COMMIT;
        float* As = sm + (it % 3) * S_STAGE;
        float* Bs = As + 64 * SA;
        #pragma unroll
        for (int kk = 0; kk < 32; kk += 8) {
            uint32_t a[2][4], bfrag[2][2];
            #pragma unroll
            for (int t = 0; t < 2; t++) {
                int rb = R + t * 16 + ar;
                a[t][0] = __float_as_uint(As[rb * SA + kk + ac]);
                a[t][1] = __float_as_uint(As[(rb + 8) * SA + kk + ac]);
                a[t][2] = __float_as_uint(As[rb * SA + kk + ac + 4]);
                a[t][3] = __float_as_uint(As[(rb + 8) * SA + kk + ac + 4]);
            }
            #pragma unroll
            for (int n = 0; n < 2; n++) {
                int cb = C + n * 8 + ar;
                bfrag[n][0] = __float_as_uint(Bs[cb * SA + kk + ac]);
                bfrag[n][1] = __float_as_uint(Bs[cb * SA + kk + ac + 4]);
            }
            #pragma unroll
            for (int t = 0; t < 2; t++)
                #pragma unroll
                for (int n = 0; n < 2; n++)
                    mma_tf32(acc[t][n], a[t], bfrag[n]);
        }
    }
    __syncthreads();

    float* Cs = sm;
    #pragma unroll
    for (int t = 0; t < 2; t++) {
        #pragma unroll
        for (int n = 0; n < 2; n++) {
            int row = R + t * 16 + ar;
            int col = C + n * 8 + 2 * ac;
            Cs[col * 65 + row]            = acc[t][n][0];
            Cs[(col + 1) * 65 + row]      = acc[t][n][1];
            Cs[col * 65 + row + 8]        = acc[t][n][2];
            Cs[(col + 1) * 65 + row + 8]  = acc[t][n][3];
        }
    }
    __syncthreads();
    float* dst = g_spart + kc * SPART_SZ;
    #pragma unroll
    for (int l = 0; l < 16; l++) {
        int e = l * 256 + tid;
        int j = e >> 6, m = e & 63;
        dst[((b * NH + j) << 12) + m0 + m] = Cs[j * 65 + m];
    }
}

// ---------------------------------------------------------------------------
// 4) softmax: sum 4 split-K partials, softmax over compacted prefix
__global__ void k_softmax() {
    __shared__ float red[256];
    int row = blockIdx.x;
    int b = row >> 6;
    int cnt = g_cnt[b];
    const float* p0 = g_spart + row * SS;
    float* sc = g_scores + row * SS;
    int tid = threadIdx.x;
    float v[16];
    float mx = -FLT_MAX;
    #pragma unroll
    for (int k = 0; k < 16; k++) {
        int s = k * 256 + tid;
        float val = -FLT_MAX;
        if (s < cnt)
            val = p0[s] + p0[SPART_SZ + s] + p0[2 * SPART_SZ + s] + p0[3 * SPART_SZ + s];
        v[k] = val;
        mx = fmaxf(mx, val);
    }
    red[tid] = mx; __syncthreads();
    for (int o = 128; o; o >>= 1) { if (tid < o) red[tid] = fmaxf(red[tid], red[tid + o]); __syncthreads(); }
    mx = red[0]; __syncthreads();
    float sum = 0.f;
    #pragma unroll
    for (int k = 0; k < 16; k++) { v[k] = __expf(v[k] - mx); sum += v[k]; }
    red[tid] = sum; __syncthreads();
    for (int o = 128; o; o >>= 1) { if (tid < o) red[tid] += red[tid + o]; __syncthreads(); }
    float inv = 1.f / red[0];
    #pragma unroll
    for (int k = 0; k < 16; k++) sc[k * 256 + tid] = __uint_as_float(f2tf(v[k] * inv));
}

// ---------------------------------------------------------------------------
// 5) agg: CTA tile 64j x 64i, split-s x2, 3-stage cp.async
#define SHS 72
#define G_STAGE (64 * SA + 32 * SHS)
__global__ void k_agg(const float* __restrict__ H) {
    extern __shared__ float sm[];
    int tid = threadIdx.x;
    int lane = tid & 31, w = tid >> 5;
    int wm = w & 1, wn = w >> 1;
    int R = wm * 32, C = wn * 16;
    int b = blockIdx.y;
    int i0 = blockIdx.x * 64;
    int sc_id = blockIdx.z;
    int ar = lane >> 2, ac = lane & 3;
    int cnt = g_cnt[b];
    int NIT_total = (cnt + 31) >> 5;
    int half = (NIT_total + 1) >> 1;
    int it0 = sc_id * half;
    int it1 = min(NIT_total, it0 + half);

    uint32_t smem_u32 = (uint32_t)__cvta_generic_to_shared(sm);

    float acc[2][2][4];
    #pragma unroll
    for (int t = 0; t < 2; t++)
        #pragma unroll
        for (int n = 0; n < 2; n++)
            #pragma unroll
            for (int q = 0; q < 4; q++) acc[t][n][q] = 0.f;

    const float* Hb = H + (size_t)b * SS * HID;
    const float* A  = g_scores + b * NH * SS;
    const int* sidx = g_sidx + b * SS;

    int lra = tid >> 3;
    int lca = (tid & 7) * 4;
    int hr = tid >> 4;
    int hc = (tid & 15) * 4;

    auto issue = [&](int stage, int it) {
        int st = it * 32;
        uint32_t base = smem_u32 + stage * G_STAGE * 4;
        #pragma unroll
        for (int p = 0; p < 2; p++) {
            int r = p * 32 + lra;
            cp16(base + (r * SA + lca) * 4, &A[r * SS + st + lca]);
        }
        uint32_t hbase = base + 64 * SA * 4;
        #pragma unroll
        for (int p = 0; p < 2; p++) {
            int r = p * 16 + hr;
            int gi = sidx[st + r];
            cp16(hbase + (r * SHS + hc) * 4, &Hb[(size_t)gi * HID + i0 + hc]);
        }
    };

    if (it0 < it1) {
        issue(0, it0); CP_COMMIT;
        if (it0 + 1 < it1) issue(1, it0 + 1);
        CP_COMMIT;
        for (int it = it0; it < it1; it++) {
            CP_WAIT1;
            __syncthreads();
            if (it + 2 < it1) issue((it - it0 + 2) % 3, it + 2);
            CP_COMMIT;
            float* As = sm + ((it - it0) % 3) * G_STAGE;
            float* Hs = As + 64 * SA;
            #pragma unroll
            for (int kk = 0; kk < 32; kk += 8) {
                uint32_t a[2][4], bfr[2][2];
                #pragma unroll
                for (int t = 0; t < 2; t++) {
                    int rb = R + t * 16 + ar;
                    a[t][0] = __float_as_uint(As[rb * SA + kk + ac]);
                    a[t][1] = __float_as_uint(As[(rb + 8) * SA + kk + ac]);
                    a[t][2] = __float_as_uint(As[rb * SA + kk + ac + 4]);
                    a[t][3] = __float_as_uint(As[(rb + 8) * SA + kk + ac + 4]);
                }
                #pragma unroll
                for (int n = 0; n < 2; n++) {
                    int cb = C + n * 8 + ar;
                    bfr[n][0] = __float_as_uint(Hs[(kk + ac) * SHS + cb]);
                    bfr[n][1] = __float_as_uint(Hs[(kk + ac + 4) * SHS + cb]);
                }
                #pragma unroll
                for (int t = 0; t < 2; t++)
                    #pragma unroll
                    for (int n = 0; n < 2; n++)
                        mma_tf32(acc[t][n], a[t], bfr[n]);
            }
        }
    }

    float* dst = g_apart + sc_id * APART_SZ;
    #pragma unroll
    for (int t = 0; t < 2; t++) {
        #pragma unroll
        for (int n = 0; n < 2; n++) {
            int j = R + t * 16 + ar;
            int i = C + n * 8 + 2 * ac;
            float2 v0 = make_float2(acc[t][n][0], acc[t][n][1]);
            float2 v1 = make_float2(acc[t][n][2], acc[t][n][3]);
            *(float2*)&dst[(size_t)(b * NH + j) * HID + i0 + i]     = v0;
            *(float2*)&dst[(size_t)(b * NH + j + 8) * HID + i0 + i] = v1;
        }
    }
}

// ---------------------------------------------------------------------------
// 6) mid, split-K x4 with atomic epilogue; sums the 2 agg partials
__global__ void k_mid(const float* __restrict__ Wv) {
    __shared__ float As[8][65];
    __shared__ float Bs[64][65];
    int h = blockIdx.x, b = blockIdx.y, kc = blockIdx.z;
    int tid = threadIdx.x;
    float acc0 = 0.f, acc1 = 0.f;
    int o0 = tid, o1 = tid + 256;
    int n0 = o0 >> 6, d0 = o0 & 63;
    int n1 = o1 >> 6, d1 = o1 & 63;
    int k0 = kc * (HID / 4), k1 = k0 + HID / 4;
    for (int kt = k0; kt < k1; kt += 64) {
        {
            int e = tid; int r = e >> 6, c = e & 63;
            size_t ix = (size_t)(b * NH + h * SLOTS + r) * HID + kt + c;
            As[r][c] = g_apart[ix] + g_apart[APART_SZ + ix];
            e = tid + 256; r = e >> 6; c = e & 63;
            ix = (size_t)(b * NH + h * SLOTS + r) * HID + kt + c;
            As[r][c] = g_apart[ix] + g_apart[APART_SZ + ix];
        }
        #pragma unroll
        for (int l = 0; l < 16; l++) {
            int e = tid + l * 256;
            int r = e >> 6, c = e & 63;
            Bs[r][c] = Wv[(h * HD + r) * HID + kt + c];
        }
        __syncthreads();
        #pragma unroll
        for (int k = 0; k < 64; k++) {
            acc0 += As[n0][k] * Bs[d0][k];
            acc1 += As[n1][k] * Bs[d1][k];
        }
        __syncthreads();
    }
    atomicAdd(&g_mid[(b * SLOTS + n0) * BD + h * HD + d0], acc0);
    atomicAdd(&g_mid[(b * SLOTS + n1) * BD + h * HD + d1], acc1);
}

// ---------------------------------------------------------------------------
// 7) final, o-tile 64
__global__ void k_final(const float* __restrict__ Wo, float* __restrict__ out) {
    __shared__ float As[32][65];
    __shared__ float Bs[64][65];
    int tid = threadIdx.x;
    int tx = tid & 15, ty = tid >> 4;
    int o0 = blockIdx.x * 64;
    float acc[2][4] = {};
    for (int kt = 0; kt < BD; kt += 64) {
        #pragma unroll
        for (int l = 0; l < 8; l++) {
            int e = tid + l * 256;
            int r = e >> 6, c = e & 63;
            As[r][c] = g_mid[r * BD + kt + c];
        }
        #pragma unroll
        for (int l = 0; l < 16; l++) {
            int e = tid + l * 256;
            int r = e >> 6, c = e & 63;
            Bs[r][c] = Wo[(o0 + r) * BD + kt + c];
        }
        __syncthreads();
        #pragma unroll
        for (int k = 0; k < 64; k++) {
            float a[2], bb[4];
            #pragma unroll
            for (int x = 0; x < 2; x++) a[x] = As[ty * 2 + x][k];
            #pragma unroll
            for (int y = 0; y < 4; y++) bb[y] = Bs[tx * 4 + y][k];
            #pragma unroll
            for (int x = 0; x < 2; x++)
                #pragma unroll
                for (int y = 0; y < 4; y++) acc[x][y] += a[x] * bb[y];
        }
        __syncthreads();
    }
    #pragma unroll
    for (int x = 0; x < 2; x++)
        #pragma unroll
        for (int y = 0; y < 4; y++)
            out[(ty * 2 + x) * HID + o0 + tx * 4 + y] = acc[x][y];
}

// ---------------------------------------------------------------------------
extern "C" void kernel_launch(void* const* d_in, const int* in_sizes, int n_in,
                              void* d_out, int out_size) {
    const float* H    = (const float*)d_in[0];
    const int*   mask = (const int*)d_in[1];
    const float* ms   = (const float*)d_in[2];
    const float* Wq   = (const float*)d_in[3];
    const float* Wk   = (const float*)d_in[4];
    const float* Wv   = (const float*)d_in[5];
    const float* Wo   = (const float*)d_in[6];
    float* out = (float*)d_out;

    static int attr_done = 0;
    if (!attr_done) {
        cudaFuncSetAttribute(k_scores, cudaFuncAttributeMaxDynamicSharedMemorySize,
                             3 * S_STAGE * 4);
        cudaFuncSetAttribute(k_agg, cudaFuncAttributeMaxDynamicSharedMemorySize,
                             3 * G_STAGE * 4);
        attr_done = 1;
    }

    k_compact<<<BB, 256>>>(mask);
    k_qproj <<<512, 256>>>(ms, Wq);
    k_qk    <<<dim3(HID / 256, NH), 256>>>(Wk);
    k_scores<<<dim3(SS / 64, BB, 4), 256, 3 * S_STAGE * 4>>>(H);
    k_softmax<<<BB * NH, 256>>>();
    k_agg   <<<dim3(HID / 64, BB, 2), 256, 3 * G_STAGE * 4>>>(H);
    k_mid   <<<dim3(HEADS, BB, 4), 256>>>(Wv);
    k_final <<<HID / 64, 256>>>(Wo, out);
}